// round 1
// baseline (speedup 1.0000x reference)
#include <cuda_runtime.h>
#include <cuda_bf16.h>

#define N_USERS 100000
#define N_ITEMS 50000
#define N_TOTAL 150000
#define DIM 64
#define BATCH 4096

// Scratch: three ping-pong embedding buffers (38.4 MB each), static device globals
// (no allocation allowed in kernel_launch).
__device__ float g_A[N_TOTAL * DIM];
__device__ float g_B[N_TOTAL * DIM];
__device__ float g_ACC[N_TOTAL * DIM];

// ACC = E0 ; A = 0   (A is the first spmm destination)
__global__ void k_init(const float4* __restrict__ E0,
                       float4* __restrict__ ACC,
                       float4* __restrict__ A, int n4) {
    int i = blockIdx.x * blockDim.x + threadIdx.x;
    if (i < n4) {
        ACC[i] = E0[i];
        A[i] = make_float4(0.f, 0.f, 0.f, 0.f);
    }
}

// ACC += S ; Z = 0   (Z is the next spmm destination)
__global__ void k_upd(float4* __restrict__ ACC,
                      const float4* __restrict__ S,
                      float4* __restrict__ Z, int n4) {
    int i = blockIdx.x * blockDim.x + threadIdx.x;
    if (i < n4) {
        float4 a = ACC[i];
        float4 s = S[i];
        a.x += s.x; a.y += s.y; a.z += s.z; a.w += s.w;
        ACC[i] = a;
        Z[i] = make_float4(0.f, 0.f, 0.f, 0.f);
    }
}

// dst[row[e]] += vals[e] * src[col[e]]   (16 threads per edge, float4 lanes,
// vectorized L2 reduction red.global.add.v4.f32)
__global__ void k_spmm(const int* __restrict__ row,
                       const int* __restrict__ col,
                       const float* __restrict__ vals,
                       const float* __restrict__ src,
                       float* __restrict__ dst, int nnz) {
    int t = blockIdx.x * blockDim.x + threadIdx.x;
    int e = t >> 4;
    int q = t & 15;
    if (e >= nnz) return;

    int r = __ldg(row + e);
    int c = __ldg(col + e);
    float v = __ldg(vals + e);

    const float4* s = reinterpret_cast<const float4*>(src + (size_t)c * DIM) + q;
    float4 x = __ldg(s);
    x.x *= v; x.y *= v; x.z *= v; x.w *= v;

    float* d = dst + (size_t)r * DIM + (q << 2);
    asm volatile("red.global.add.v4.f32 [%0], {%1, %2, %3, %4};"
                 :: "l"(d), "f"(x.x), "f"(x.y), "f"(x.z), "f"(x.w)
                 : "memory");
}

// out[0..2] = (ACC + L3)[gathered rows] / 4 ; out[3..5] = E0[gathered rows]
__global__ void k_gather(const int* __restrict__ users,
                         const int* __restrict__ pos,
                         const int* __restrict__ neg,
                         const float* __restrict__ E0,
                         const float* __restrict__ ACC,
                         const float* __restrict__ L3,
                         float* __restrict__ out) {
    int t = blockIdx.x * blockDim.x + threadIdx.x;
    if (t >= BATCH * DIM) return;
    int b = t >> 6;
    int d = t & 63;
    const int S = BATCH * DIM;

    int u = __ldg(users + b);
    int p = N_USERS + __ldg(pos + b);
    int n = N_USERS + __ldg(neg + b);

    size_t iu = (size_t)u * DIM + d;
    size_t ip = (size_t)p * DIM + d;
    size_t in_ = (size_t)n * DIM + d;

    out[0 * S + t] = (ACC[iu] + L3[iu]) * 0.25f;
    out[1 * S + t] = (ACC[ip] + L3[ip]) * 0.25f;
    out[2 * S + t] = (ACC[in_] + L3[in_]) * 0.25f;
    out[3 * S + t] = E0[iu];
    out[4 * S + t] = E0[ip];
    out[5 * S + t] = E0[in_];
}

extern "C" void kernel_launch(void* const* d_in, const int* in_sizes, int n_in,
                              void* d_out, int out_size) {
    const int*   users = (const int*)d_in[0];
    const int*   pos   = (const int*)d_in[1];
    const int*   neg   = (const int*)d_in[2];
    const float* E0    = (const float*)d_in[3];
    const int*   row   = (const int*)d_in[4];
    const int*   col   = (const int*)d_in[5];
    const float* vals  = (const float*)d_in[6];
    const int    nnz   = in_sizes[4];

    float *A, *B, *ACC;
    cudaGetSymbolAddress((void**)&A,   g_A);
    cudaGetSymbolAddress((void**)&B,   g_B);
    cudaGetSymbolAddress((void**)&ACC, g_ACC);

    const int n4 = N_TOTAL * DIM / 4;
    const int TB = 256;
    const int gridElem = (n4 + TB - 1) / TB;

    // ACC = E0 ; A = 0
    k_init<<<gridElem, TB>>>((const float4*)E0, (float4*)ACC, (float4*)A, n4);

    long long spmmT = (long long)nnz * 16;
    int spmmGrid = (int)((spmmT + TB - 1) / TB);

    // Layer 1: A = S @ E0
    k_spmm<<<spmmGrid, TB>>>(row, col, vals, E0, A, nnz);
    // ACC += A ; B = 0
    k_upd<<<gridElem, TB>>>((float4*)ACC, (const float4*)A, (float4*)B, n4);
    // Layer 2: B = S @ A
    k_spmm<<<spmmGrid, TB>>>(row, col, vals, A, B, nnz);
    // ACC += B ; A = 0
    k_upd<<<gridElem, TB>>>((float4*)ACC, (const float4*)B, (float4*)A, n4);
    // Layer 3: A = S @ B   (ACC += A is fused into the gather)
    k_spmm<<<spmmGrid, TB>>>(row, col, vals, B, A, nnz);

    // Gather outputs
    int gGrid = (BATCH * DIM + TB - 1) / TB;
    k_gather<<<gGrid, TB>>>(users, pos, neg, E0, ACC, A, (float*)d_out);
}

// round 2
// speedup vs baseline: 1.3581x; 1.3581x over previous
#include <cuda_runtime.h>
#include <cuda_bf16.h>

#define N_USERS  100000
#define N_TOTAL  150000
#define DIM      64
#define BATCH    4096
#define NNZ_MAX  1300000

#define SCAN_TILE 4096                 // 1024 threads x 4 items
#define NB ((N_TOTAL + SCAN_TILE - 1) / SCAN_TILE)   // 37

// Static scratch (no allocation allowed in kernel_launch)
__device__ float g_A[N_TOTAL * DIM];
__device__ float g_B[N_TOTAL * DIM];
__device__ float g_ACC[N_TOTAL * DIM];
__device__ int   g_cnt[N_TOTAL];
__device__ int   g_rowptr[N_TOTAL];
__device__ int   g_cursor[N_TOTAL];
__device__ int2  g_edge[NNZ_MAX];      // {col, val bits} packed 8B
__device__ int   g_bsum[64];
__device__ int   g_boff[64];

// ---------------------------------------------------------------------------
// ACC = E0 ; zero histogram counters
__global__ void k_init(const float4* __restrict__ E0, int n4) {
    int i = blockIdx.x * blockDim.x + threadIdx.x;
    if (i < n4) reinterpret_cast<float4*>(g_ACC)[i] = E0[i];
    if (i < N_TOTAL) g_cnt[i] = 0;
}

// histogram of row ids
__global__ void k_hist(const int* __restrict__ row, int nnz) {
    int e = blockIdx.x * blockDim.x + threadIdx.x;
    if (e < nnz) atomicAdd(&g_cnt[__ldg(row + e)], 1);
}

// per-block partial sums of g_cnt
__global__ void k_scan1() {
    __shared__ int sh[32];
    int base = blockIdx.x * SCAN_TILE + threadIdx.x * 4;
    int s = 0;
#pragma unroll
    for (int k = 0; k < 4; k++) {
        int idx = base + k;
        if (idx < N_TOTAL) s += g_cnt[idx];
    }
#pragma unroll
    for (int o = 16; o > 0; o >>= 1) s += __shfl_down_sync(0xffffffffu, s, o);
    if ((threadIdx.x & 31) == 0) sh[threadIdx.x >> 5] = s;
    __syncthreads();
    if (threadIdx.x < 32) {
        int v = sh[threadIdx.x];
#pragma unroll
        for (int o = 16; o > 0; o >>= 1) v += __shfl_down_sync(0xffffffffu, v, o);
        if (threadIdx.x == 0) g_bsum[blockIdx.x] = v;
    }
}

// exclusive scan of block sums (tiny, serial)
__global__ void k_scan2(int nb) {
    if (threadIdx.x == 0) {
        int acc = 0;
        for (int i = 0; i < nb; i++) { g_boff[i] = acc; acc += g_bsum[i]; }
    }
}

// per-block exclusive scan -> rowptr & cursor
__global__ void k_scan3() {
    __shared__ int warpsum[32];
    int tid  = threadIdx.x;
    int lane = tid & 31, wid = tid >> 5;
    int base = blockIdx.x * SCAN_TILE + tid * 4;

    int c[4];
#pragma unroll
    for (int k = 0; k < 4; k++) {
        int idx = base + k;
        c[k] = (idx < N_TOTAL) ? g_cnt[idx] : 0;
    }
    int t = c[0] + c[1] + c[2] + c[3];

    // inclusive warp scan of thread totals
    int x = t;
#pragma unroll
    for (int o = 1; o < 32; o <<= 1) {
        int y = __shfl_up_sync(0xffffffffu, x, o);
        if (lane >= o) x += y;
    }
    if (lane == 31) warpsum[wid] = x;
    __syncthreads();
    if (wid == 0) {
        int v = warpsum[lane];
#pragma unroll
        for (int o = 1; o < 32; o <<= 1) {
            int y = __shfl_up_sync(0xffffffffu, v, o);
            if (lane >= o) v += y;
        }
        warpsum[lane] = v;
    }
    __syncthreads();

    int woff = (wid == 0) ? 0 : warpsum[wid - 1];
    int run  = g_boff[blockIdx.x] + woff + (x - t);   // exclusive offset of this thread's first item
#pragma unroll
    for (int k = 0; k < 4; k++) {
        int idx = base + k;
        if (idx < N_TOTAL) {
            g_rowptr[idx] = run;
            g_cursor[idx] = run;
            run += c[k];
        }
    }
}

// scatter edges into CSR slots
__global__ void k_scatter(const int* __restrict__ row, const int* __restrict__ col,
                          const float* __restrict__ vals, int nnz) {
    int e = blockIdx.x * blockDim.x + threadIdx.x;
    if (e >= nnz) return;
    int r = __ldg(row + e);
    int slot = atomicAdd(&g_cursor[r], 1);
    g_edge[slot] = make_int2(__ldg(col + e), __float_as_int(__ldg(vals + e)));
}

// ---------------------------------------------------------------------------
// CSR gather SpMM: dst[r] = sum_e val * src[col], 16 threads per row (float4 lanes).
// Optionally fuses ACC[r] += dst[r].
template <bool FUSE_ACC>
__global__ void k_spmm(const float* __restrict__ src, float* __restrict__ dst) {
    int t = blockIdx.x * blockDim.x + threadIdx.x;
    int r = t >> 4;
    int q = t & 15;
    if (r >= N_TOTAL) return;

    int beg = __ldg(g_rowptr + r);
    int cnt = __ldg(g_cnt + r);
    const int2* ep = g_edge + beg;

    float4 a0 = make_float4(0.f, 0.f, 0.f, 0.f);
    float4 a1 = make_float4(0.f, 0.f, 0.f, 0.f);

    int i = 0;
    for (; i + 2 <= cnt; i += 2) {
        int2 e0 = __ldg(ep + i);
        int2 e1 = __ldg(ep + i + 1);
        float v0 = __int_as_float(e0.y);
        float v1 = __int_as_float(e1.y);
        float4 x0 = __ldg(reinterpret_cast<const float4*>(src + (size_t)e0.x * DIM) + q);
        float4 x1 = __ldg(reinterpret_cast<const float4*>(src + (size_t)e1.x * DIM) + q);
        a0.x += v0 * x0.x; a0.y += v0 * x0.y; a0.z += v0 * x0.z; a0.w += v0 * x0.w;
        a1.x += v1 * x1.x; a1.y += v1 * x1.y; a1.z += v1 * x1.z; a1.w += v1 * x1.w;
    }
    if (i < cnt) {
        int2 e0 = __ldg(ep + i);
        float v0 = __int_as_float(e0.y);
        float4 x0 = __ldg(reinterpret_cast<const float4*>(src + (size_t)e0.x * DIM) + q);
        a0.x += v0 * x0.x; a0.y += v0 * x0.y; a0.z += v0 * x0.z; a0.w += v0 * x0.w;
    }
    a0.x += a1.x; a0.y += a1.y; a0.z += a1.z; a0.w += a1.w;

    size_t o = (size_t)r * DIM + (q << 2);
    *reinterpret_cast<float4*>(dst + o) = a0;

    if (FUSE_ACC) {
        float4* ap = reinterpret_cast<float4*>(g_ACC + o);
        float4 a = *ap;
        a.x += a0.x; a.y += a0.y; a.z += a0.z; a.w += a0.w;
        *ap = a;
    }
}

// ---------------------------------------------------------------------------
// out[0..2] = (ACC + L3)[rows] / 4 ; out[3..5] = E0[rows]
__global__ void k_gather(const int* __restrict__ users, const int* __restrict__ pos,
                         const int* __restrict__ neg, const float* __restrict__ E0,
                         const float* __restrict__ L3, float* __restrict__ out) {
    int t = blockIdx.x * blockDim.x + threadIdx.x;
    if (t >= BATCH * DIM) return;
    int b = t >> 6;
    int d = t & 63;
    const int S = BATCH * DIM;

    int u = __ldg(users + b);
    int p = N_USERS + __ldg(pos + b);
    int n = N_USERS + __ldg(neg + b);

    size_t iu = (size_t)u * DIM + d;
    size_t ip = (size_t)p * DIM + d;
    size_t in_ = (size_t)n * DIM + d;

    out[0 * S + t] = (g_ACC[iu] + L3[iu]) * 0.25f;
    out[1 * S + t] = (g_ACC[ip] + L3[ip]) * 0.25f;
    out[2 * S + t] = (g_ACC[in_] + L3[in_]) * 0.25f;
    out[3 * S + t] = E0[iu];
    out[4 * S + t] = E0[ip];
    out[5 * S + t] = E0[in_];
}

extern "C" void kernel_launch(void* const* d_in, const int* in_sizes, int n_in,
                              void* d_out, int out_size) {
    const int*   users = (const int*)d_in[0];
    const int*   pos   = (const int*)d_in[1];
    const int*   neg   = (const int*)d_in[2];
    const float* E0    = (const float*)d_in[3];
    const int*   row   = (const int*)d_in[4];
    const int*   col   = (const int*)d_in[5];
    const float* vals  = (const float*)d_in[6];
    const int    nnz   = in_sizes[4];

    float *A, *B;
    cudaGetSymbolAddress((void**)&A, g_A);
    cudaGetSymbolAddress((void**)&B, g_B);

    const int TB = 256;
    const int n4 = N_TOTAL * DIM / 4;

    // init + CSR build
    k_init<<<(n4 + TB - 1) / TB, TB>>>((const float4*)E0, n4);
    k_hist<<<(nnz + TB - 1) / TB, TB>>>(row, nnz);
    k_scan1<<<NB, 1024>>>();
    k_scan2<<<1, 32>>>(NB);
    k_scan3<<<NB, 1024>>>();
    k_scatter<<<(nnz + TB - 1) / TB, TB>>>(row, col, vals, nnz);

    // 3 propagation layers (gather SpMM, ACC fused; layer 3 ACC fused in k_gather)
    const int spmmGrid = (N_TOTAL * 16 + TB - 1) / TB;
    k_spmm<true ><<<spmmGrid, TB>>>(E0, A);   // A = S @ E0 ; ACC += A
    k_spmm<true ><<<spmmGrid, TB>>>(A,  B);   // B = S @ A  ; ACC += B
    k_spmm<false><<<spmmGrid, TB>>>(B,  A);   // A = S @ B

    // outputs
    k_gather<<<(BATCH * DIM + TB - 1) / TB, TB>>>(users, pos, neg, E0, A, (float*)d_out);
}

// round 3
// speedup vs baseline: 1.9802x; 1.4580x over previous
#include <cuda_runtime.h>
#include <cuda_bf16.h>

#define N_USERS  100000
#define N_TOTAL  150000
#define DIM      64
#define BATCH    4096
#define NNZ_MAX  1300000

#define SCAN_TILE 4096                                  // 1024 threads x 4 items
#define NB ((N_TOTAL + SCAN_TILE - 1) / SCAN_TILE)      // 37 blocks (all resident)

// Static scratch (no allocation allowed anywhere)
__device__ float g_A[N_TOTAL * DIM];
__device__ float g_B[N_TOTAL * DIM];
__device__ int   g_cnt[N_TOTAL];
__device__ int   g_rowptr[N_TOTAL];
__device__ int   g_cursor[N_TOTAL];
__device__ int2  g_edge[NNZ_MAX];      // {col, val bits}
__device__ int   g_blockAgg[64];
__device__ int   g_aggReady[64];

// ---------------------------------------------------------------------------
// zero histogram counters + scan flags (must run first every call)
__global__ void k_zero() {
    int i = blockIdx.x * blockDim.x + threadIdx.x;
    if (i < N_TOTAL) g_cnt[i] = 0;
    if (i < 64) { g_aggReady[i] = 0; g_blockAgg[i] = 0; }
}

// histogram of row ids (RED, no return)
__global__ void k_hist(const int* __restrict__ row, int nnz) {
    int e = blockIdx.x * blockDim.x + threadIdx.x;
    if (e < nnz) atomicAdd(&g_cnt[__ldg(row + e)], 1);
}

// single-pass exclusive scan -> rowptr & cursor (37 blocks, aggregate lookback;
// all blocks resident concurrently so spinning is deadlock-free)
__global__ void k_scan() {
    __shared__ int warpsum[32];
    __shared__ int s_aggs[64];
    __shared__ int s_prev;
    int tid  = threadIdx.x;
    int lane = tid & 31, wid = tid >> 5;
    int base = blockIdx.x * SCAN_TILE + tid * 4;

    int c[4];
#pragma unroll
    for (int k = 0; k < 4; k++) {
        int idx = base + k;
        c[k] = (idx < N_TOTAL) ? g_cnt[idx] : 0;
    }
    int t = c[0] + c[1] + c[2] + c[3];

    // inclusive warp scan of thread totals
    int x = t;
#pragma unroll
    for (int o = 1; o < 32; o <<= 1) {
        int y = __shfl_up_sync(0xffffffffu, x, o);
        if (lane >= o) x += y;
    }
    if (lane == 31) warpsum[wid] = x;
    __syncthreads();
    if (wid == 0) {
        int v = warpsum[lane];
#pragma unroll
        for (int o = 1; o < 32; o <<= 1) {
            int y = __shfl_up_sync(0xffffffffu, v, o);
            if (lane >= o) v += y;
        }
        warpsum[lane] = v;
    }
    __syncthreads();

    int woff = (wid == 0) ? 0 : warpsum[wid - 1];
    int blockTotal = warpsum[31];

    // publish this block's aggregate
    if (tid == 0) {
        g_blockAgg[blockIdx.x] = blockTotal;
        __threadfence();
        atomicExch(&g_aggReady[blockIdx.x], 1);
    }

    // lookback: thread j < bid fetches block j's aggregate
    if (tid < blockIdx.x) {
        while (atomicAdd(&g_aggReady[tid], 0) == 0) { }
        __threadfence();
        s_aggs[tid] = g_blockAgg[tid];
    }
    __syncthreads();
    if (tid == 0) {
        int p = 0;
        for (int j = 0; j < blockIdx.x; j++) p += s_aggs[j];
        s_prev = p;
    }
    __syncthreads();

    int run = s_prev + woff + (x - t);   // exclusive offset of this thread's first item
#pragma unroll
    for (int k = 0; k < 4; k++) {
        int idx = base + k;
        if (idx < N_TOTAL) {
            g_rowptr[idx] = run;
            g_cursor[idx] = run;
            run += c[k];
        }
    }
}

// scatter edges into CSR slots
__global__ void k_scatter(const int* __restrict__ row, const int* __restrict__ col,
                          const float* __restrict__ vals, int nnz) {
    int e = blockIdx.x * blockDim.x + threadIdx.x;
    if (e >= nnz) return;
    int r = __ldg(row + e);
    int slot = atomicAdd(&g_cursor[r], 1);
    g_edge[slot] = make_int2(__ldg(col + e), __float_as_int(__ldg(vals + e)));
}

// ---------------------------------------------------------------------------
// CSR gather SpMM: dst[r] = sum_e val * src[col]; 16 threads per row, float4 lanes
__global__ void k_spmm(const float* __restrict__ src, float* __restrict__ dst) {
    int t = blockIdx.x * blockDim.x + threadIdx.x;
    int r = t >> 4;
    int q = t & 15;
    if (r >= N_TOTAL) return;

    int beg = __ldg(g_rowptr + r);
    int cnt = __ldg(g_cnt + r);
    const int2* ep = g_edge + beg;

    float4 a0 = make_float4(0.f, 0.f, 0.f, 0.f);
    float4 a1 = make_float4(0.f, 0.f, 0.f, 0.f);

    int i = 0;
    for (; i + 2 <= cnt; i += 2) {
        int2 e0 = __ldg(ep + i);
        int2 e1 = __ldg(ep + i + 1);
        float v0 = __int_as_float(e0.y);
        float v1 = __int_as_float(e1.y);
        float4 x0 = __ldg(reinterpret_cast<const float4*>(src + (size_t)e0.x * DIM) + q);
        float4 x1 = __ldg(reinterpret_cast<const float4*>(src + (size_t)e1.x * DIM) + q);
        a0.x += v0 * x0.x; a0.y += v0 * x0.y; a0.z += v0 * x0.z; a0.w += v0 * x0.w;
        a1.x += v1 * x1.x; a1.y += v1 * x1.y; a1.z += v1 * x1.z; a1.w += v1 * x1.w;
    }
    if (i < cnt) {
        int2 e0 = __ldg(ep + i);
        float v0 = __int_as_float(e0.y);
        float4 x0 = __ldg(reinterpret_cast<const float4*>(src + (size_t)e0.x * DIM) + q);
        a0.x += v0 * x0.x; a0.y += v0 * x0.y; a0.z += v0 * x0.z; a0.w += v0 * x0.w;
    }
    a0.x += a1.x; a0.y += a1.y; a0.z += a1.z; a0.w += a1.w;

    *reinterpret_cast<float4*>(dst + (size_t)r * DIM + (q << 2)) = a0;
}

// ---------------------------------------------------------------------------
// Fused layer-3 + output: for each gathered node r, compute c = (S@B)[r] on the
// fly (CSR reduce over B), then out = (E0[r]+A[r]+B[r]+c)/4 and E0[r].
__global__ void k_out(const int* __restrict__ users, const int* __restrict__ pos,
                      const int* __restrict__ neg, const float* __restrict__ E0,
                      float* __restrict__ out) {
    int t = blockIdx.x * blockDim.x + threadIdx.x;
    if (t >= 3 * BATCH * 16) return;
    int s = t >> 16;            // section: 0=user 1=pos 2=neg   (BATCH*16 = 65536)
    int rem = t & 65535;
    int b = rem >> 4;
    int q = rem & 15;

    int node;
    if (s == 0)      node = __ldg(users + b);
    else if (s == 1) node = N_USERS + __ldg(pos + b);
    else             node = N_USERS + __ldg(neg + b);

    // layer-3 row reduction
    int beg = __ldg(g_rowptr + node);
    int cnt = __ldg(g_cnt + node);
    const int2* ep = g_edge + beg;

    float4 c = make_float4(0.f, 0.f, 0.f, 0.f);
    for (int i = 0; i < cnt; i++) {
        int2 e = __ldg(ep + i);
        float v = __int_as_float(e.y);
        float4 x = __ldg(reinterpret_cast<const float4*>(g_B + (size_t)e.x * DIM) + q);
        c.x += v * x.x; c.y += v * x.y; c.z += v * x.z; c.w += v * x.w;
    }

    size_t off = (size_t)node * DIM + (q << 2);
    float4 e0 = *reinterpret_cast<const float4*>(E0 + off);
    float4 a  = *reinterpret_cast<const float4*>(g_A + off);
    float4 bb = *reinterpret_cast<const float4*>(g_B + off);

    float4 f;
    f.x = (e0.x + a.x + bb.x + c.x) * 0.25f;
    f.y = (e0.y + a.y + bb.y + c.y) * 0.25f;
    f.z = (e0.z + a.z + bb.z + c.z) * 0.25f;
    f.w = (e0.w + a.w + bb.w + c.w) * 0.25f;

    const int S = BATCH * DIM;
    int o = b * DIM + (q << 2);
    *reinterpret_cast<float4*>(out + (size_t)s * S + o)       = f;
    *reinterpret_cast<float4*>(out + (size_t)(s + 3) * S + o) = e0;
}

extern "C" void kernel_launch(void* const* d_in, const int* in_sizes, int n_in,
                              void* d_out, int out_size) {
    const int*   users = (const int*)d_in[0];
    const int*   pos   = (const int*)d_in[1];
    const int*   neg   = (const int*)d_in[2];
    const float* E0    = (const float*)d_in[3];
    const int*   row   = (const int*)d_in[4];
    const int*   col   = (const int*)d_in[5];
    const float* vals  = (const float*)d_in[6];
    const int    nnz   = in_sizes[4];

    float *A, *B;
    cudaGetSymbolAddress((void**)&A, g_A);
    cudaGetSymbolAddress((void**)&B, g_B);

    const int TB = 256;

    // CSR build
    k_zero<<<(N_TOTAL + TB - 1) / TB, TB>>>();
    k_hist<<<(nnz + TB - 1) / TB, TB>>>(row, nnz);
    k_scan<<<NB, 1024>>>();
    k_scatter<<<(nnz + TB - 1) / TB, TB>>>(row, col, vals, nnz);

    // 2 full propagation layers
    const int spmmGrid = (N_TOTAL * 16 + TB - 1) / TB;
    k_spmm<<<spmmGrid, TB>>>(E0, A);   // A = S @ E0
    k_spmm<<<spmmGrid, TB>>>(A,  B);   // B = S @ A

    // fused layer 3 + gather
    int outThreads = 3 * BATCH * 16;
    k_out<<<(outThreads + TB - 1) / TB, TB>>>(users, pos, neg, E0, (float*)d_out);
}

// round 4
// speedup vs baseline: 2.0373x; 1.0289x over previous
#include <cuda_runtime.h>
#include <cuda_bf16.h>

#define N_USERS  100000
#define N_TOTAL  150000
#define DIM      64
#define BATCH    4096
#define NNZ_MAX  1400000     // 1.2M edges + up to 150k pad slots

#define SCAN_TILE 4096                                  // 1024 threads x 4 items
#define NB ((N_TOTAL + SCAN_TILE - 1) / SCAN_TILE)      // 37 blocks (all resident)

// Static scratch (no allocation allowed anywhere)
__device__ float g_A[N_TOTAL * DIM];
__device__ float g_B[N_TOTAL * DIM];
__device__ int   g_cnt[N_TOTAL];      // true row degree (spmm loop bound)
__device__ int   g_rowptr[N_TOTAL];   // padded-to-even exclusive scan (16B-aligned segs)
__device__ int   g_cursor[N_TOTAL];
__device__ int2  g_edge[NNZ_MAX];     // {col, val bits}
__device__ int   g_blockAgg[64];
__device__ int   g_aggReady[64];

// ---------------------------------------------------------------------------
// zero histogram counters + scan flags
__global__ void k_zero() {
    int i = blockIdx.x * blockDim.x + threadIdx.x;
    int4* p = reinterpret_cast<int4*>(g_cnt);
    if (i < N_TOTAL / 4) p[i] = make_int4(0, 0, 0, 0);
    if (i < 64) { g_aggReady[i] = 0; g_blockAgg[i] = 0; }
}

// histogram of row ids: 4 edges/thread, 4 independent REDs
__global__ void k_hist(const int* __restrict__ row, int nnz) {
    int t = blockIdx.x * blockDim.x + threadIdx.x;
    int base = t * 4;
    if (base + 4 <= nnz) {
        int4 r = __ldg(reinterpret_cast<const int4*>(row + base));
        atomicAdd(&g_cnt[r.x], 1);
        atomicAdd(&g_cnt[r.y], 1);
        atomicAdd(&g_cnt[r.z], 1);
        atomicAdd(&g_cnt[r.w], 1);
    } else {
        for (int e = base; e < nnz; e++) atomicAdd(&g_cnt[__ldg(row + e)], 1);
    }
}

// single-pass exclusive scan of PADDED counts -> rowptr & cursor
// (37 blocks, aggregate lookback; all resident so spin is deadlock-free)
__global__ void k_scan() {
    __shared__ int warpsum[32];
    __shared__ int s_aggs[64];
    __shared__ int s_prev;
    int tid  = threadIdx.x;
    int lane = tid & 31, wid = tid >> 5;
    int base = blockIdx.x * SCAN_TILE + tid * 4;

    int c[4];
#pragma unroll
    for (int k = 0; k < 4; k++) {
        int idx = base + k;
        c[k] = (idx < N_TOTAL) ? ((g_cnt[idx] + 1) & ~1) : 0;   // pad to even
    }
    int t = c[0] + c[1] + c[2] + c[3];

    int x = t;
#pragma unroll
    for (int o = 1; o < 32; o <<= 1) {
        int y = __shfl_up_sync(0xffffffffu, x, o);
        if (lane >= o) x += y;
    }
    if (lane == 31) warpsum[wid] = x;
    __syncthreads();
    if (wid == 0) {
        int v = warpsum[lane];
#pragma unroll
        for (int o = 1; o < 32; o <<= 1) {
            int y = __shfl_up_sync(0xffffffffu, v, o);
            if (lane >= o) v += y;
        }
        warpsum[lane] = v;
    }
    __syncthreads();

    int woff = (wid == 0) ? 0 : warpsum[wid - 1];
    int blockTotal = warpsum[31];

    if (tid == 0) {
        g_blockAgg[blockIdx.x] = blockTotal;
        __threadfence();
        atomicExch(&g_aggReady[blockIdx.x], 1);
    }
    if (tid < blockIdx.x) {
        while (atomicAdd(&g_aggReady[tid], 0) == 0) { }
        __threadfence();
        s_aggs[tid] = g_blockAgg[tid];
    }
    __syncthreads();
    if (tid == 0) {
        int p = 0;
        for (int j = 0; j < blockIdx.x; j++) p += s_aggs[j];
        s_prev = p;
    }
    __syncthreads();

    int run = s_prev + woff + (x - t);
#pragma unroll
    for (int k = 0; k < 4; k++) {
        int idx = base + k;
        if (idx < N_TOTAL) {
            g_rowptr[idx] = run;
            g_cursor[idx] = run;
            run += c[k];
        }
    }
}

// scatter edges into CSR slots: 4 edges/thread, 4 independent atomic->store chains
__global__ void k_scatter(const int* __restrict__ row, const int* __restrict__ col,
                          const float* __restrict__ vals, int nnz) {
    int t = blockIdx.x * blockDim.x + threadIdx.x;
    int base = t * 4;
    if (base + 4 <= nnz) {
        int4   r = __ldg(reinterpret_cast<const int4*>(row + base));
        int4   c = __ldg(reinterpret_cast<const int4*>(col + base));
        float4 v = __ldg(reinterpret_cast<const float4*>(vals + base));
        int s0 = atomicAdd(&g_cursor[r.x], 1);
        int s1 = atomicAdd(&g_cursor[r.y], 1);
        int s2 = atomicAdd(&g_cursor[r.z], 1);
        int s3 = atomicAdd(&g_cursor[r.w], 1);
        g_edge[s0] = make_int2(c.x, __float_as_int(v.x));
        g_edge[s1] = make_int2(c.y, __float_as_int(v.y));
        g_edge[s2] = make_int2(c.z, __float_as_int(v.z));
        g_edge[s3] = make_int2(c.w, __float_as_int(v.w));
    } else {
        for (int e = base; e < nnz; e++) {
            int rr = __ldg(row + e);
            int slot = atomicAdd(&g_cursor[rr], 1);
            g_edge[slot] = make_int2(__ldg(col + e), __float_as_int(__ldg(vals + e)));
        }
    }
}

// ---------------------------------------------------------------------------
// CSR gather SpMM: dst[r] = sum_e val * src[col]; 16 threads per row, float4 lanes.
// Edge segments are 16B-aligned; int4 loads fetch 2 edges. Unroll 4 -> 4 gather
// chains in flight per iteration.
__global__ void k_spmm(const float* __restrict__ src, float* __restrict__ dst) {
    int t = blockIdx.x * blockDim.x + threadIdx.x;
    int r = t >> 4;
    int q = t & 15;
    if (r >= N_TOTAL) return;

    int beg = __ldg(g_rowptr + r);
    int cnt = __ldg(g_cnt + r);
    const int2* ep = g_edge + beg;

    float4 a0 = make_float4(0.f, 0.f, 0.f, 0.f);
    float4 a1 = make_float4(0.f, 0.f, 0.f, 0.f);

    int i = 0;
    for (; i + 4 <= cnt; i += 4) {
        int4 e01 = __ldg(reinterpret_cast<const int4*>(ep + i));
        int4 e23 = __ldg(reinterpret_cast<const int4*>(ep + i + 2));
        float4 x0 = __ldg(reinterpret_cast<const float4*>(src + (size_t)e01.x * DIM) + q);
        float4 x1 = __ldg(reinterpret_cast<const float4*>(src + (size_t)e01.z * DIM) + q);
        float4 x2 = __ldg(reinterpret_cast<const float4*>(src + (size_t)e23.x * DIM) + q);
        float4 x3 = __ldg(reinterpret_cast<const float4*>(src + (size_t)e23.z * DIM) + q);
        float v0 = __int_as_float(e01.y);
        float v1 = __int_as_float(e01.w);
        float v2 = __int_as_float(e23.y);
        float v3 = __int_as_float(e23.w);
        a0.x += v0 * x0.x; a0.y += v0 * x0.y; a0.z += v0 * x0.z; a0.w += v0 * x0.w;
        a1.x += v1 * x1.x; a1.y += v1 * x1.y; a1.z += v1 * x1.z; a1.w += v1 * x1.w;
        a0.x += v2 * x2.x; a0.y += v2 * x2.y; a0.z += v2 * x2.z; a0.w += v2 * x2.w;
        a1.x += v3 * x3.x; a1.y += v3 * x3.y; a1.z += v3 * x3.z; a1.w += v3 * x3.w;
    }
    for (; i < cnt; i++) {
        int2 e0 = __ldg(ep + i);
        float v0 = __int_as_float(e0.y);
        float4 x0 = __ldg(reinterpret_cast<const float4*>(src + (size_t)e0.x * DIM) + q);
        a0.x += v0 * x0.x; a0.y += v0 * x0.y; a0.z += v0 * x0.z; a0.w += v0 * x0.w;
    }
    a0.x += a1.x; a0.y += a1.y; a0.z += a1.z; a0.w += a1.w;

    *reinterpret_cast<float4*>(dst + (size_t)r * DIM + (q << 2)) = a0;
}

// ---------------------------------------------------------------------------
// Fused layer-3 + output: c = (S@B)[node] on the fly; out = (E0+A+B+c)/4, E0.
__global__ void k_out(const int* __restrict__ users, const int* __restrict__ pos,
                      const int* __restrict__ neg, const float* __restrict__ E0,
                      float* __restrict__ out) {
    int t = blockIdx.x * blockDim.x + threadIdx.x;
    if (t >= 3 * BATCH * 16) return;
    int s = t >> 16;            // section: 0=user 1=pos 2=neg (BATCH*16 = 65536)
    int rem = t & 65535;
    int b = rem >> 4;
    int q = rem & 15;

    int node;
    if (s == 0)      node = __ldg(users + b);
    else if (s == 1) node = N_USERS + __ldg(pos + b);
    else             node = N_USERS + __ldg(neg + b);

    int beg = __ldg(g_rowptr + node);
    int cnt = __ldg(g_cnt + node);
    const int2* ep = g_edge + beg;

    float4 c0 = make_float4(0.f, 0.f, 0.f, 0.f);
    float4 c1 = make_float4(0.f, 0.f, 0.f, 0.f);
    int i = 0;
    for (; i + 2 <= cnt; i += 2) {
        int4 e01 = __ldg(reinterpret_cast<const int4*>(ep + i));
        float v0 = __int_as_float(e01.y);
        float v1 = __int_as_float(e01.w);
        float4 x0 = __ldg(reinterpret_cast<const float4*>(g_B + (size_t)e01.x * DIM) + q);
        float4 x1 = __ldg(reinterpret_cast<const float4*>(g_B + (size_t)e01.z * DIM) + q);
        c0.x += v0 * x0.x; c0.y += v0 * x0.y; c0.z += v0 * x0.z; c0.w += v0 * x0.w;
        c1.x += v1 * x1.x; c1.y += v1 * x1.y; c1.z += v1 * x1.z; c1.w += v1 * x1.w;
    }
    if (i < cnt) {
        int2 e = __ldg(ep + i);
        float v = __int_as_float(e.y);
        float4 x = __ldg(reinterpret_cast<const float4*>(g_B + (size_t)e.x * DIM) + q);
        c0.x += v * x.x; c0.y += v * x.y; c0.z += v * x.z; c0.w += v * x.w;
    }
    c0.x += c1.x; c0.y += c1.y; c0.z += c1.z; c0.w += c1.w;

    size_t off = (size_t)node * DIM + (q << 2);
    float4 e0 = *reinterpret_cast<const float4*>(E0 + off);
    float4 a  = *reinterpret_cast<const float4*>(g_A + off);
    float4 bb = *reinterpret_cast<const float4*>(g_B + off);

    float4 f;
    f.x = (e0.x + a.x + bb.x + c0.x) * 0.25f;
    f.y = (e0.y + a.y + bb.y + c0.y) * 0.25f;
    f.z = (e0.z + a.z + bb.z + c0.z) * 0.25f;
    f.w = (e0.w + a.w + bb.w + c0.w) * 0.25f;

    const int S = BATCH * DIM;
    int o = b * DIM + (q << 2);
    *reinterpret_cast<float4*>(out + (size_t)s * S + o)       = f;
    *reinterpret_cast<float4*>(out + (size_t)(s + 3) * S + o) = e0;
}

extern "C" void kernel_launch(void* const* d_in, const int* in_sizes, int n_in,
                              void* d_out, int out_size) {
    const int*   users = (const int*)d_in[0];
    const int*   pos   = (const int*)d_in[1];
    const int*   neg   = (const int*)d_in[2];
    const float* E0    = (const float*)d_in[3];
    const int*   row   = (const int*)d_in[4];
    const int*   col   = (const int*)d_in[5];
    const float* vals  = (const float*)d_in[6];
    const int    nnz   = in_sizes[4];

    float *A, *B;
    cudaGetSymbolAddress((void**)&A, g_A);
    cudaGetSymbolAddress((void**)&B, g_B);

    const int TB = 256;

    // CSR build
    k_zero<<<(N_TOTAL / 4 + TB - 1) / TB, TB>>>();
    int quads = (nnz + 3) / 4;
    k_hist<<<(quads + TB - 1) / TB, TB>>>(row, nnz);
    k_scan<<<NB, 1024>>>();
    k_scatter<<<(quads + TB - 1) / TB, TB>>>(row, col, vals, nnz);

    // 2 full propagation layers
    const int spmmGrid = (N_TOTAL * 16 + TB - 1) / TB;
    k_spmm<<<spmmGrid, TB>>>(E0, A);   // A = S @ E0
    k_spmm<<<spmmGrid, TB>>>(A,  B);   // B = S @ A

    // fused layer 3 + gather
    int outThreads = 3 * BATCH * 16;
    k_out<<<(outThreads + TB - 1) / TB, TB>>>(users, pos, neg, E0, (float*)d_out);
}

// round 6
// speedup vs baseline: 2.4666x; 1.2107x over previous
#include <cuda_runtime.h>
#include <cuda_fp16.h>

#define N_USERS  100000
#define N_TOTAL  150000
#define DIM      64
#define BATCH    4096
#define NNZ_MAX  1400000     // 1.2M edges + up to 150k pad slots

#define SCAN_TILE 4096                                  // 1024 threads x 4 items
#define NB ((N_TOTAL + SCAN_TILE - 1) / SCAN_TILE)      // 37 blocks (all resident)

// Static scratch (no allocation allowed anywhere)
__device__ __half g_E0h[N_TOTAL * DIM];   // fp16 copy of E0
__device__ __half g_A[N_TOTAL * DIM];     // layer-1 output (fp16)
__device__ __half g_B[N_TOTAL * DIM];     // layer-2 output (fp16)
__device__ int   g_cnt[N_TOTAL];          // true row degree
__device__ int   g_rowptr[N_TOTAL];       // padded-to-even exclusive scan
__device__ int   g_cursor[N_TOTAL];
__device__ int2  g_edge[NNZ_MAX];         // {col, val bits}; pad slots = {0, 0.0f}
__device__ int   g_blockAgg[64];
__device__ int   g_aggReady[64];

// reinterpret helpers (no dedicated intrinsics for half2<->uint bit-cast)
__device__ __forceinline__ __half2 u2h2(unsigned u) {
    __half2 h; *reinterpret_cast<unsigned*>(&h) = u; return h;
}
__device__ __forceinline__ unsigned h22u(__half2 h) {
    return *reinterpret_cast<unsigned*>(&h);
}

// ---------------------------------------------------------------------------
// prep: convert E0 -> fp16, zero counters + scan flags
__global__ void k_prep(const float4* __restrict__ E0) {
    int i = blockIdx.x * blockDim.x + threadIdx.x;
    const int n8 = N_TOTAL * DIM / 8;       // each thread converts 8 floats
    if (i < n8) {
        float4 f0 = __ldg(E0 + i * 2);
        float4 f1 = __ldg(E0 + i * 2 + 1);
        uint4 h;
        h.x = h22u(__floats2half2_rn(f0.x, f0.y));
        h.y = h22u(__floats2half2_rn(f0.z, f0.w));
        h.z = h22u(__floats2half2_rn(f1.x, f1.y));
        h.w = h22u(__floats2half2_rn(f1.z, f1.w));
        reinterpret_cast<uint4*>(g_E0h)[i] = h;
    }
    if (i < N_TOTAL / 4) reinterpret_cast<int4*>(g_cnt)[i] = make_int4(0, 0, 0, 0);
    if (i < 64) { g_aggReady[i] = 0; g_blockAgg[i] = 0; }
}

// histogram of row ids: 4 edges/thread
__global__ void k_hist(const int* __restrict__ row, int nnz) {
    int t = blockIdx.x * blockDim.x + threadIdx.x;
    int base = t * 4;
    if (base + 4 <= nnz) {
        int4 r = __ldg(reinterpret_cast<const int4*>(row + base));
        atomicAdd(&g_cnt[r.x], 1);
        atomicAdd(&g_cnt[r.y], 1);
        atomicAdd(&g_cnt[r.z], 1);
        atomicAdd(&g_cnt[r.w], 1);
    } else {
        for (int e = base; e < nnz; e++) atomicAdd(&g_cnt[__ldg(row + e)], 1);
    }
}

// single-pass exclusive scan of padded counts -> rowptr & cursor; writes the
// zero-valued pad edge for odd-degree rows so spmm can always read edge pairs.
__global__ void k_scan() {
    __shared__ int warpsum[32];
    __shared__ int s_aggs[64];
    __shared__ int s_prev;
    int tid  = threadIdx.x;
    int lane = tid & 31, wid = tid >> 5;
    int base = blockIdx.x * SCAN_TILE + tid * 4;

    int cc[4], cp[4];
#pragma unroll
    for (int k = 0; k < 4; k++) {
        int idx = base + k;
        cc[k] = (idx < N_TOTAL) ? g_cnt[idx] : 0;
        cp[k] = (cc[k] + 1) & ~1;                 // padded to even
    }
    int t = cp[0] + cp[1] + cp[2] + cp[3];

    int x = t;
#pragma unroll
    for (int o = 1; o < 32; o <<= 1) {
        int y = __shfl_up_sync(0xffffffffu, x, o);
        if (lane >= o) x += y;
    }
    if (lane == 31) warpsum[wid] = x;
    __syncthreads();
    if (wid == 0) {
        int v = warpsum[lane];
#pragma unroll
        for (int o = 1; o < 32; o <<= 1) {
            int y = __shfl_up_sync(0xffffffffu, v, o);
            if (lane >= o) v += y;
        }
        warpsum[lane] = v;
    }
    __syncthreads();

    if (tid == 0) {
        g_blockAgg[blockIdx.x] = warpsum[31];
        __threadfence();
        atomicExch(&g_aggReady[blockIdx.x], 1);
    }
    if (tid < blockIdx.x) {
        while (atomicAdd(&g_aggReady[tid], 0) == 0) { }
        __threadfence();
        s_aggs[tid] = g_blockAgg[tid];
    }
    __syncthreads();
    if (tid == 0) {
        int p = 0;
        for (int j = 0; j < blockIdx.x; j++) p += s_aggs[j];
        s_prev = p;
    }
    __syncthreads();

    int woff = (wid == 0) ? 0 : warpsum[wid - 1];
    int run = s_prev + woff + (x - t);
#pragma unroll
    for (int k = 0; k < 4; k++) {
        int idx = base + k;
        if (idx < N_TOTAL) {
            g_rowptr[idx] = run;
            g_cursor[idx] = run;
            if (cc[k] & 1) g_edge[run + cc[k]] = make_int2(0, 0);   // pad edge, val=0
            run += cp[k];
        }
    }
}

// scatter edges into CSR slots: 2 edges/thread (atomic throughput is the floor;
// large grid keeps latency hidden)
__global__ void k_scatter(const int* __restrict__ row, const int* __restrict__ col,
                          const float* __restrict__ vals, int nnz) {
    int t = blockIdx.x * blockDim.x + threadIdx.x;
    int base = t * 2;
    if (base + 2 <= nnz) {
        int2   r = __ldg(reinterpret_cast<const int2*>(row + base));
        int2   c = __ldg(reinterpret_cast<const int2*>(col + base));
        float2 v = __ldg(reinterpret_cast<const float2*>(vals + base));
        int s0 = atomicAdd(&g_cursor[r.x], 1);
        int s1 = atomicAdd(&g_cursor[r.y], 1);
        g_edge[s0] = make_int2(c.x, __float_as_int(v.x));
        g_edge[s1] = make_int2(c.y, __float_as_int(v.y));
    } else if (base < nnz) {
        int rr = __ldg(row + base);
        int slot = atomicAdd(&g_cursor[rr], 1);
        g_edge[slot] = make_int2(__ldg(col + base), __float_as_int(__ldg(vals + base)));
    }
}

// ---------------------------------------------------------------------------
// accumulate uint4 (8 halfs) * v into float2[4]
__device__ __forceinline__ void fma_h8v(float2 acc[4], uint4 h, float v) {
    float2 p;
    p = __half22float2(u2h2(h.x)); acc[0].x += v * p.x; acc[0].y += v * p.y;
    p = __half22float2(u2h2(h.y)); acc[1].x += v * p.x; acc[1].y += v * p.y;
    p = __half22float2(u2h2(h.z)); acc[2].x += v * p.x; acc[2].y += v * p.y;
    p = __half22float2(u2h2(h.w)); acc[3].x += v * p.x; acc[3].y += v * p.y;
}

// CSR gather SpMM (fp16 src -> fp16 dst, fp32 accum): 8 threads/row, 8 dims/lane.
__global__ void k_spmm(const __half* __restrict__ src, __half* __restrict__ dst) {
    int t = blockIdx.x * blockDim.x + threadIdx.x;
    int r = t >> 3;
    int q = t & 7;
    if (r >= N_TOTAL) return;

    int beg = __ldg(g_rowptr + r);
    int cnt2 = (__ldg(g_cnt + r) + 1) & ~1;     // padded count (pad edges have v=0)
    const int2* ep = g_edge + beg;
    const uint4* src4 = reinterpret_cast<const uint4*>(src);

    float2 a0[4] = {{0,0},{0,0},{0,0},{0,0}};
    float2 a1[4] = {{0,0},{0,0},{0,0},{0,0}};

    int i = 0;
    for (; i + 4 <= cnt2; i += 4) {
        int4 e01 = __ldg(reinterpret_cast<const int4*>(ep + i));
        int4 e23 = __ldg(reinterpret_cast<const int4*>(ep + i + 2));
        uint4 h0 = __ldg(src4 + (size_t)e01.x * 8 + q);
        uint4 h1 = __ldg(src4 + (size_t)e01.z * 8 + q);
        uint4 h2 = __ldg(src4 + (size_t)e23.x * 8 + q);
        uint4 h3 = __ldg(src4 + (size_t)e23.z * 8 + q);
        fma_h8v(a0, h0, __int_as_float(e01.y));
        fma_h8v(a1, h1, __int_as_float(e01.w));
        fma_h8v(a0, h2, __int_as_float(e23.y));
        fma_h8v(a1, h3, __int_as_float(e23.w));
    }
    if (i < cnt2) {
        int4 e01 = __ldg(reinterpret_cast<const int4*>(ep + i));
        uint4 h0 = __ldg(src4 + (size_t)e01.x * 8 + q);
        uint4 h1 = __ldg(src4 + (size_t)e01.z * 8 + q);
        fma_h8v(a0, h0, __int_as_float(e01.y));
        fma_h8v(a1, h1, __int_as_float(e01.w));
    }
#pragma unroll
    for (int k = 0; k < 4; k++) { a0[k].x += a1[k].x; a0[k].y += a1[k].y; }

    uint4 o;
    o.x = h22u(__floats2half2_rn(a0[0].x, a0[0].y));
    o.y = h22u(__floats2half2_rn(a0[1].x, a0[1].y));
    o.z = h22u(__floats2half2_rn(a0[2].x, a0[2].y));
    o.w = h22u(__floats2half2_rn(a0[3].x, a0[3].y));
    reinterpret_cast<uint4*>(dst)[(size_t)r * 8 + q] = o;
}

// ---------------------------------------------------------------------------
// Fused layer-3 + output: c = (S@B)[node] on the fly; out = (E0+A+B+c)/4, E0.
// 8 threads per node row, 8 dims/lane.
__global__ void k_out(const int* __restrict__ users, const int* __restrict__ pos,
                      const int* __restrict__ neg, const float* __restrict__ E0,
                      float* __restrict__ out) {
    int t = blockIdx.x * blockDim.x + threadIdx.x;
    if (t >= 3 * BATCH * 8) return;
    int s = t >> 15;            // BATCH*8 = 32768
    int rem = t & 32767;
    int b = rem >> 3;
    int q = rem & 7;

    int node;
    if (s == 0)      node = __ldg(users + b);
    else if (s == 1) node = N_USERS + __ldg(pos + b);
    else             node = N_USERS + __ldg(neg + b);

    int beg = __ldg(g_rowptr + node);
    int cnt2 = (__ldg(g_cnt + node) + 1) & ~1;
    const int2* ep = g_edge + beg;
    const uint4* B4 = reinterpret_cast<const uint4*>(g_B);

    float2 c0[4] = {{0,0},{0,0},{0,0},{0,0}};
    for (int i = 0; i < cnt2; i += 2) {
        int4 e01 = __ldg(reinterpret_cast<const int4*>(ep + i));
        uint4 h0 = __ldg(B4 + (size_t)e01.x * 8 + q);
        uint4 h1 = __ldg(B4 + (size_t)e01.z * 8 + q);
        fma_h8v(c0, h0, __int_as_float(e01.y));
        fma_h8v(c0, h1, __int_as_float(e01.w));
    }

    size_t off4 = (size_t)node * 8 + q;                  // uint4 index into half rows
    uint4 ha = __ldg(reinterpret_cast<const uint4*>(g_A) + off4);
    uint4 hb = __ldg(B4 + off4);
    size_t offf = (size_t)node * DIM + q * 8;            // float index
    float4 e00 = __ldg(reinterpret_cast<const float4*>(E0 + offf));
    float4 e01v = __ldg(reinterpret_cast<const float4*>(E0 + offf + 4));

    float2 pa, pb;
    float outv[8];
    pa = __half22float2(u2h2(ha.x)); pb = __half22float2(u2h2(hb.x));
    outv[0] = (e00.x + pa.x + pb.x + c0[0].x) * 0.25f;
    outv[1] = (e00.y + pa.y + pb.y + c0[0].y) * 0.25f;
    pa = __half22float2(u2h2(ha.y)); pb = __half22float2(u2h2(hb.y));
    outv[2] = (e00.z + pa.x + pb.x + c0[1].x) * 0.25f;
    outv[3] = (e00.w + pa.y + pb.y + c0[1].y) * 0.25f;
    pa = __half22float2(u2h2(ha.z)); pb = __half22float2(u2h2(hb.z));
    outv[4] = (e01v.x + pa.x + pb.x + c0[2].x) * 0.25f;
    outv[5] = (e01v.y + pa.y + pb.y + c0[2].y) * 0.25f;
    pa = __half22float2(u2h2(ha.w)); pb = __half22float2(u2h2(hb.w));
    outv[6] = (e01v.z + pa.x + pb.x + c0[3].x) * 0.25f;
    outv[7] = (e01v.w + pa.y + pb.y + c0[3].y) * 0.25f;

    const int S = BATCH * DIM;
    int o = b * DIM + q * 8;
    float4* op = reinterpret_cast<float4*>(out + (size_t)s * S + o);
    op[0] = make_float4(outv[0], outv[1], outv[2], outv[3]);
    op[1] = make_float4(outv[4], outv[5], outv[6], outv[7]);
    float4* oe = reinterpret_cast<float4*>(out + (size_t)(s + 3) * S + o);
    oe[0] = e00;
    oe[1] = e01v;
}

extern "C" void kernel_launch(void* const* d_in, const int* in_sizes, int n_in,
                              void* d_out, int out_size) {
    const int*   users = (const int*)d_in[0];
    const int*   pos   = (const int*)d_in[1];
    const int*   neg   = (const int*)d_in[2];
    const float* E0    = (const float*)d_in[3];
    const int*   row   = (const int*)d_in[4];
    const int*   col   = (const int*)d_in[5];
    const float* vals  = (const float*)d_in[6];
    const int    nnz   = in_sizes[4];

    __half *E0h, *A, *B;
    cudaGetSymbolAddress((void**)&E0h, g_E0h);
    cudaGetSymbolAddress((void**)&A,   g_A);
    cudaGetSymbolAddress((void**)&B,   g_B);

    const int TB = 256;

    // prep + CSR build
    const int n8 = N_TOTAL * DIM / 8;
    k_prep<<<(n8 + TB - 1) / TB, TB>>>((const float4*)E0);
    int quads = (nnz + 3) / 4;
    k_hist<<<(quads + TB - 1) / TB, TB>>>(row, nnz);
    k_scan<<<NB, 1024>>>();
    int pairs = (nnz + 1) / 2;
    k_scatter<<<(pairs + TB - 1) / TB, TB>>>(row, col, vals, nnz);

    // 2 full propagation layers (fp16 storage, fp32 accumulate)
    const int spmmGrid = (N_TOTAL * 8 + TB - 1) / TB;
    k_spmm<<<spmmGrid, TB>>>(E0h, A);   // A = S @ E0
    k_spmm<<<spmmGrid, TB>>>(A,   B);   // B = S @ A

    // fused layer 3 + gather
    int outThreads = 3 * BATCH * 8;
    k_out<<<(outThreads + TB - 1) / TB, TB>>>(users, pos, neg, E0, (float*)d_out);
}

// round 7
// speedup vs baseline: 2.5640x; 1.0395x over previous
#include <cuda_runtime.h>
#include <cuda_fp16.h>

#define N_USERS  100000
#define N_TOTAL  150000
#define DIM      64
#define BATCH    4096
#define NNZ_MAX  1400000     // 1.2M edges + up to 150k pad slots

#define SCAN_TILE 4096                                  // 1024 threads x 4 items
#define NB ((N_TOTAL + SCAN_TILE - 1) / SCAN_TILE)      // 37 blocks (all resident)

// Static scratch (no allocation allowed anywhere)
__device__ __half g_E0h[N_TOTAL * DIM];   // fp16 copy of E0
__device__ __half g_A[N_TOTAL * DIM];     // layer-1 output (fp16)
__device__ __half g_B[N_TOTAL * DIM];     // layer-2 output (fp16)
__device__ int   g_cnt[N_TOTAL];          // true row degree
__device__ int   g_rowptr[N_TOTAL];       // padded-to-even exclusive scan
__device__ int   g_rank[NNZ_MAX];         // intra-row rank per edge (from hist)
__device__ int2  g_edge[NNZ_MAX];         // {col, val bits}; pad slots = {0, 0.0f}
__device__ int   g_blockAgg[64];
__device__ int   g_aggReady[64];

// reinterpret helpers (no dedicated intrinsics for half2<->uint bit-cast)
__device__ __forceinline__ __half2 u2h2(unsigned u) {
    __half2 h; *reinterpret_cast<unsigned*>(&h) = u; return h;
}
__device__ __forceinline__ unsigned h22u(__half2 h) {
    return *reinterpret_cast<unsigned*>(&h);
}

// ---------------------------------------------------------------------------
// prep: convert E0 -> fp16, zero counters + scan flags
__global__ void k_prep(const float4* __restrict__ E0) {
    int i = blockIdx.x * blockDim.x + threadIdx.x;
    const int n8 = N_TOTAL * DIM / 8;       // each thread converts 8 floats
    if (i < n8) {
        float4 f0 = __ldg(E0 + i * 2);
        float4 f1 = __ldg(E0 + i * 2 + 1);
        uint4 h;
        h.x = h22u(__floats2half2_rn(f0.x, f0.y));
        h.y = h22u(__floats2half2_rn(f0.z, f0.w));
        h.z = h22u(__floats2half2_rn(f1.x, f1.y));
        h.w = h22u(__floats2half2_rn(f1.z, f1.w));
        reinterpret_cast<uint4*>(g_E0h)[i] = h;
    }
    if (i < N_TOTAL / 4) reinterpret_cast<int4*>(g_cnt)[i] = make_int4(0, 0, 0, 0);
    if (i < 64) { g_aggReady[i] = 0; g_blockAgg[i] = 0; }
}

// histogram of row ids, capturing each edge's intra-row rank.
// 4 edges/thread: 4 independent atomic-return chains + one coalesced int4 store.
__global__ void k_hist(const int* __restrict__ row, int nnz) {
    int t = blockIdx.x * blockDim.x + threadIdx.x;
    int base = t * 4;
    if (base + 4 <= nnz) {
        int4 r = __ldg(reinterpret_cast<const int4*>(row + base));
        int4 k;
        k.x = atomicAdd(&g_cnt[r.x], 1);
        k.y = atomicAdd(&g_cnt[r.y], 1);
        k.z = atomicAdd(&g_cnt[r.z], 1);
        k.w = atomicAdd(&g_cnt[r.w], 1);
        *reinterpret_cast<int4*>(g_rank + base) = k;
    } else {
        for (int e = base; e < nnz; e++)
            g_rank[e] = atomicAdd(&g_cnt[__ldg(row + e)], 1);
    }
}

// single-pass exclusive scan of padded counts -> rowptr; writes the zero-valued
// pad edge for odd-degree rows so spmm can always read edge pairs.
__global__ void k_scan() {
    __shared__ int warpsum[32];
    __shared__ int s_aggs[64];
    __shared__ int s_prev;
    int tid  = threadIdx.x;
    int lane = tid & 31, wid = tid >> 5;
    int base = blockIdx.x * SCAN_TILE + tid * 4;

    int cc[4], cp[4];
#pragma unroll
    for (int k = 0; k < 4; k++) {
        int idx = base + k;
        cc[k] = (idx < N_TOTAL) ? g_cnt[idx] : 0;
        cp[k] = (cc[k] + 1) & ~1;                 // padded to even
    }
    int t = cp[0] + cp[1] + cp[2] + cp[3];

    int x = t;
#pragma unroll
    for (int o = 1; o < 32; o <<= 1) {
        int y = __shfl_up_sync(0xffffffffu, x, o);
        if (lane >= o) x += y;
    }
    if (lane == 31) warpsum[wid] = x;
    __syncthreads();
    if (wid == 0) {
        int v = warpsum[lane];
#pragma unroll
        for (int o = 1; o < 32; o <<= 1) {
            int y = __shfl_up_sync(0xffffffffu, v, o);
            if (lane >= o) v += y;
        }
        warpsum[lane] = v;
    }
    __syncthreads();

    if (tid == 0) {
        g_blockAgg[blockIdx.x] = warpsum[31];
        __threadfence();
        atomicExch(&g_aggReady[blockIdx.x], 1);
    }
    if (tid < blockIdx.x) {
        while (atomicAdd(&g_aggReady[tid], 0) == 0) { }
        __threadfence();
        s_aggs[tid] = g_blockAgg[tid];
    }
    __syncthreads();
    if (tid == 0) {
        int p = 0;
        for (int j = 0; j < blockIdx.x; j++) p += s_aggs[j];
        s_prev = p;
    }
    __syncthreads();

    int woff = (wid == 0) ? 0 : warpsum[wid - 1];
    int run = s_prev + woff + (x - t);
#pragma unroll
    for (int k = 0; k < 4; k++) {
        int idx = base + k;
        if (idx < N_TOTAL) {
            g_rowptr[idx] = run;
            if (cc[k] & 1) g_edge[run + cc[k]] = make_int2(0, 0);   // pad edge, val=0
            run += cp[k];
        }
    }
}

// scatter edges into CSR slots — atomic-free: slot = rowptr[row] + rank[edge].
// 4 edges/thread, all loads/stores independent (high MLP).
__global__ void k_scatter(const int* __restrict__ row, const int* __restrict__ col,
                          const float* __restrict__ vals, int nnz) {
    int t = blockIdx.x * blockDim.x + threadIdx.x;
    int base = t * 4;
    if (base + 4 <= nnz) {
        int4   r = __ldg(reinterpret_cast<const int4*>(row + base));
        int4   c = __ldg(reinterpret_cast<const int4*>(col + base));
        float4 v = __ldg(reinterpret_cast<const float4*>(vals + base));
        int4   k = *reinterpret_cast<const int4*>(g_rank + base);
        int p0 = __ldg(g_rowptr + r.x);
        int p1 = __ldg(g_rowptr + r.y);
        int p2 = __ldg(g_rowptr + r.z);
        int p3 = __ldg(g_rowptr + r.w);
        g_edge[p0 + k.x] = make_int2(c.x, __float_as_int(v.x));
        g_edge[p1 + k.y] = make_int2(c.y, __float_as_int(v.y));
        g_edge[p2 + k.z] = make_int2(c.z, __float_as_int(v.z));
        g_edge[p3 + k.w] = make_int2(c.w, __float_as_int(v.w));
    } else {
        for (int e = base; e < nnz; e++) {
            int rr = __ldg(row + e);
            int slot = __ldg(g_rowptr + rr) + g_rank[e];
            g_edge[slot] = make_int2(__ldg(col + e), __float_as_int(__ldg(vals + e)));
        }
    }
}

// ---------------------------------------------------------------------------
// accumulate uint4 (8 halfs) * v into float2[4]
__device__ __forceinline__ void fma_h8v(float2 acc[4], uint4 h, float v) {
    float2 p;
    p = __half22float2(u2h2(h.x)); acc[0].x += v * p.x; acc[0].y += v * p.y;
    p = __half22float2(u2h2(h.y)); acc[1].x += v * p.x; acc[1].y += v * p.y;
    p = __half22float2(u2h2(h.z)); acc[2].x += v * p.x; acc[2].y += v * p.y;
    p = __half22float2(u2h2(h.w)); acc[3].x += v * p.x; acc[3].y += v * p.y;
}

// CSR gather SpMM (fp16 src -> fp16 dst, fp32 accum): 8 threads/row, 8 dims/lane.
__global__ void k_spmm(const __half* __restrict__ src, __half* __restrict__ dst) {
    int t = blockIdx.x * blockDim.x + threadIdx.x;
    int r = t >> 3;
    int q = t & 7;
    if (r >= N_TOTAL) return;

    int beg = __ldg(g_rowptr + r);
    int cnt2 = (__ldg(g_cnt + r) + 1) & ~1;     // padded count (pad edges have v=0)
    const int2* ep = g_edge + beg;
    const uint4* src4 = reinterpret_cast<const uint4*>(src);

    float2 a0[4] = {{0,0},{0,0},{0,0},{0,0}};
    float2 a1[4] = {{0,0},{0,0},{0,0},{0,0}};

    int i = 0;
    for (; i + 4 <= cnt2; i += 4) {
        int4 e01 = __ldg(reinterpret_cast<const int4*>(ep + i));
        int4 e23 = __ldg(reinterpret_cast<const int4*>(ep + i + 2));
        uint4 h0 = __ldg(src4 + (size_t)e01.x * 8 + q);
        uint4 h1 = __ldg(src4 + (size_t)e01.z * 8 + q);
        uint4 h2 = __ldg(src4 + (size_t)e23.x * 8 + q);
        uint4 h3 = __ldg(src4 + (size_t)e23.z * 8 + q);
        fma_h8v(a0, h0, __int_as_float(e01.y));
        fma_h8v(a1, h1, __int_as_float(e01.w));
        fma_h8v(a0, h2, __int_as_float(e23.y));
        fma_h8v(a1, h3, __int_as_float(e23.w));
    }
    if (i < cnt2) {
        int4 e01 = __ldg(reinterpret_cast<const int4*>(ep + i));
        uint4 h0 = __ldg(src4 + (size_t)e01.x * 8 + q);
        uint4 h1 = __ldg(src4 + (size_t)e01.z * 8 + q);
        fma_h8v(a0, h0, __int_as_float(e01.y));
        fma_h8v(a1, h1, __int_as_float(e01.w));
    }
#pragma unroll
    for (int k = 0; k < 4; k++) { a0[k].x += a1[k].x; a0[k].y += a1[k].y; }

    uint4 o;
    o.x = h22u(__floats2half2_rn(a0[0].x, a0[0].y));
    o.y = h22u(__floats2half2_rn(a0[1].x, a0[1].y));
    o.z = h22u(__floats2half2_rn(a0[2].x, a0[2].y));
    o.w = h22u(__floats2half2_rn(a0[3].x, a0[3].y));
    reinterpret_cast<uint4*>(dst)[(size_t)r * 8 + q] = o;
}

// ---------------------------------------------------------------------------
// Fused layer-3 + output: c = (S@B)[node] on the fly; out = (E0+A+B+c)/4, E0.
// 8 threads per node row, 8 dims/lane.
__global__ void k_out(const int* __restrict__ users, const int* __restrict__ pos,
                      const int* __restrict__ neg, const float* __restrict__ E0,
                      float* __restrict__ out) {
    int t = blockIdx.x * blockDim.x + threadIdx.x;
    if (t >= 3 * BATCH * 8) return;
    int s = t >> 15;            // BATCH*8 = 32768
    int rem = t & 32767;
    int b = rem >> 3;
    int q = rem & 7;

    int node;
    if (s == 0)      node = __ldg(users + b);
    else if (s == 1) node = N_USERS + __ldg(pos + b);
    else             node = N_USERS + __ldg(neg + b);

    int beg = __ldg(g_rowptr + node);
    int cnt2 = (__ldg(g_cnt + node) + 1) & ~1;
    const int2* ep = g_edge + beg;
    const uint4* B4 = reinterpret_cast<const uint4*>(g_B);

    float2 c0[4] = {{0,0},{0,0},{0,0},{0,0}};
    for (int i = 0; i < cnt2; i += 2) {
        int4 e01 = __ldg(reinterpret_cast<const int4*>(ep + i));
        uint4 h0 = __ldg(B4 + (size_t)e01.x * 8 + q);
        uint4 h1 = __ldg(B4 + (size_t)e01.z * 8 + q);
        fma_h8v(c0, h0, __int_as_float(e01.y));
        fma_h8v(c0, h1, __int_as_float(e01.w));
    }

    size_t off4 = (size_t)node * 8 + q;                  // uint4 index into half rows
    uint4 ha = __ldg(reinterpret_cast<const uint4*>(g_A) + off4);
    uint4 hb = __ldg(B4 + off4);
    size_t offf = (size_t)node * DIM + q * 8;            // float index
    float4 e00 = __ldg(reinterpret_cast<const float4*>(E0 + offf));
    float4 e01v = __ldg(reinterpret_cast<const float4*>(E0 + offf + 4));

    float2 pa, pb;
    float outv[8];
    pa = __half22float2(u2h2(ha.x)); pb = __half22float2(u2h2(hb.x));
    outv[0] = (e00.x + pa.x + pb.x + c0[0].x) * 0.25f;
    outv[1] = (e00.y + pa.y + pb.y + c0[0].y) * 0.25f;
    pa = __half22float2(u2h2(ha.y)); pb = __half22float2(u2h2(hb.y));
    outv[2] = (e00.z + pa.x + pb.x + c0[1].x) * 0.25f;
    outv[3] = (e00.w + pa.y + pb.y + c0[1].y) * 0.25f;
    pa = __half22float2(u2h2(ha.z)); pb = __half22float2(u2h2(hb.z));
    outv[4] = (e01v.x + pa.x + pb.x + c0[2].x) * 0.25f;
    outv[5] = (e01v.y + pa.y + pb.y + c0[2].y) * 0.25f;
    pa = __half22float2(u2h2(ha.w)); pb = __half22float2(u2h2(hb.w));
    outv[6] = (e01v.z + pa.x + pb.x + c0[3].x) * 0.25f;
    outv[7] = (e01v.w + pa.y + pb.y + c0[3].y) * 0.25f;

    const int S = BATCH * DIM;
    int o = b * DIM + q * 8;
    float4* op = reinterpret_cast<float4*>(out + (size_t)s * S + o);
    op[0] = make_float4(outv[0], outv[1], outv[2], outv[3]);
    op[1] = make_float4(outv[4], outv[5], outv[6], outv[7]);
    float4* oe = reinterpret_cast<float4*>(out + (size_t)(s + 3) * S + o);
    oe[0] = e00;
    oe[1] = e01v;
}

extern "C" void kernel_launch(void* const* d_in, const int* in_sizes, int n_in,
                              void* d_out, int out_size) {
    const int*   users = (const int*)d_in[0];
    const int*   pos   = (const int*)d_in[1];
    const int*   neg   = (const int*)d_in[2];
    const float* E0    = (const float*)d_in[3];
    const int*   row   = (const int*)d_in[4];
    const int*   col   = (const int*)d_in[5];
    const float* vals  = (const float*)d_in[6];
    const int    nnz   = in_sizes[4];

    __half *E0h, *A, *B;
    cudaGetSymbolAddress((void**)&E0h, g_E0h);
    cudaGetSymbolAddress((void**)&A,   g_A);
    cudaGetSymbolAddress((void**)&B,   g_B);

    const int TB = 256;

    // prep + CSR build
    const int n8 = N_TOTAL * DIM / 8;
    k_prep<<<(n8 + TB - 1) / TB, TB>>>((const float4*)E0);
    int quads = (nnz + 3) / 4;
    k_hist<<<(quads + TB - 1) / TB, TB>>>(row, nnz);
    k_scan<<<NB, 1024>>>();
    k_scatter<<<(quads + TB - 1) / TB, TB>>>(row, col, vals, nnz);

    // 2 full propagation layers (fp16 storage, fp32 accumulate)
    const int spmmGrid = (N_TOTAL * 8 + TB - 1) / TB;
    k_spmm<<<spmmGrid, TB>>>(E0h, A);   // A = S @ E0
    k_spmm<<<spmmGrid, TB>>>(A,   B);   // B = S @ A

    // fused layer 3 + gather
    int outThreads = 3 * BATCH * 8;
    k_out<<<(outThreads + TB - 1) / TB, TB>>>(users, pos, neg, E0, (float*)d_out);
}

// round 8
// speedup vs baseline: 2.5736x; 1.0038x over previous
#include <cuda_runtime.h>
#include <cuda_fp16.h>

#define N_USERS  100000
#define N_TOTAL  150000
#define DIM      64
#define BATCH    4096
#define NNZ_MAX  1400000     // 1.2M edges + up to 150k pad slots

#define SCAN_TILE 4096                                  // 1024 threads x 4 items
#define NB ((N_TOTAL + SCAN_TILE - 1) / SCAN_TILE)      // 37 blocks (all resident)

// Scaled-space embeddings X_k = d_inv ⊙ E_k, fp16, with one extra zero row
// (index N_TOTAL) used as the gather target of pad edges.
__device__ __half g_X0[(N_TOTAL + 1) * DIM];
__device__ __half g_XA[(N_TOTAL + 1) * DIM];
__device__ __half g_XB[(N_TOTAL + 1) * DIM];
__device__ float g_dinv[N_TOTAL];        // (deg+1e-9)^-0.5
__device__ float g_dpos[N_TOTAL];        // (deg+1e-9)^+0.5  (to unscale)
__device__ int   g_cnt[N_TOTAL];         // true row degree
__device__ int   g_rowptr[N_TOTAL];      // padded-to-even exclusive scan
__device__ int   g_rank[NNZ_MAX];        // intra-row rank per edge (from hist)
__device__ int   g_ecol[NNZ_MAX];        // CSR column indices; pad slots = N_TOTAL
__device__ int   g_blockAgg[64];
__device__ int   g_aggReady[64];

__device__ __forceinline__ __half2 u2h2(unsigned u) {
    __half2 h; *reinterpret_cast<unsigned*>(&h) = u; return h;
}
__device__ __forceinline__ unsigned h22u(__half2 h) {
    return *reinterpret_cast<unsigned*>(&h);
}

// ---------------------------------------------------------------------------
// zero counters, scan flags, and the sentinel rows of X0/XA/XB
__global__ void k_zero() {
    int i = blockIdx.x * blockDim.x + threadIdx.x;
    if (i < N_TOTAL / 4) reinterpret_cast<int4*>(g_cnt)[i] = make_int4(0, 0, 0, 0);
    if (i < 64) { g_aggReady[i] = 0; g_blockAgg[i] = 0; }
    if (i < 8) {
        uint4 z = make_uint4(0, 0, 0, 0);
        reinterpret_cast<uint4*>(g_X0 + N_TOTAL * DIM)[i] = z;
        reinterpret_cast<uint4*>(g_XA + N_TOTAL * DIM)[i] = z;
        reinterpret_cast<uint4*>(g_XB + N_TOTAL * DIM)[i] = z;
    }
}

// histogram of row ids, capturing each edge's intra-row rank (4 edges/thread)
__global__ void k_hist(const int* __restrict__ row, int nnz) {
    int t = blockIdx.x * blockDim.x + threadIdx.x;
    int base = t * 4;
    if (base + 4 <= nnz) {
        int4 r = __ldg(reinterpret_cast<const int4*>(row + base));
        int4 k;
        k.x = atomicAdd(&g_cnt[r.x], 1);
        k.y = atomicAdd(&g_cnt[r.y], 1);
        k.z = atomicAdd(&g_cnt[r.z], 1);
        k.w = atomicAdd(&g_cnt[r.w], 1);
        *reinterpret_cast<int4*>(g_rank + base) = k;
    } else {
        for (int e = base; e < nnz; e++)
            g_rank[e] = atomicAdd(&g_cnt[__ldg(row + e)], 1);
    }
}

// single-pass exclusive scan of padded counts -> rowptr; also derives the
// degree normalizers and writes pad-edge sentinels for odd-degree rows.
__global__ void k_scan() {
    __shared__ int warpsum[32];
    __shared__ int s_aggs[64];
    __shared__ int s_prev;
    int tid  = threadIdx.x;
    int lane = tid & 31, wid = tid >> 5;
    int base = blockIdx.x * SCAN_TILE + tid * 4;

    int cc[4], cp[4];
#pragma unroll
    for (int k = 0; k < 4; k++) {
        int idx = base + k;
        cc[k] = (idx < N_TOTAL) ? g_cnt[idx] : 0;
        cp[k] = (cc[k] + 1) & ~1;                 // padded to even
    }
    int t = cp[0] + cp[1] + cp[2] + cp[3];

    int x = t;
#pragma unroll
    for (int o = 1; o < 32; o <<= 1) {
        int y = __shfl_up_sync(0xffffffffu, x, o);
        if (lane >= o) x += y;
    }
    if (lane == 31) warpsum[wid] = x;
    __syncthreads();
    if (wid == 0) {
        int v = warpsum[lane];
#pragma unroll
        for (int o = 1; o < 32; o <<= 1) {
            int y = __shfl_up_sync(0xffffffffu, v, o);
            if (lane >= o) v += y;
        }
        warpsum[lane] = v;
    }
    __syncthreads();

    if (tid == 0) {
        g_blockAgg[blockIdx.x] = warpsum[31];
        __threadfence();
        atomicExch(&g_aggReady[blockIdx.x], 1);
    }
    if (tid < blockIdx.x) {
        while (atomicAdd(&g_aggReady[tid], 0) == 0) { }
        __threadfence();
        s_aggs[tid] = g_blockAgg[tid];
    }
    __syncthreads();
    if (tid == 0) {
        int p = 0;
        for (int j = 0; j < blockIdx.x; j++) p += s_aggs[j];
        s_prev = p;
    }
    __syncthreads();

    int woff = (wid == 0) ? 0 : warpsum[wid - 1];
    int run = s_prev + woff + (x - t);
#pragma unroll
    for (int k = 0; k < 4; k++) {
        int idx = base + k;
        if (idx < N_TOTAL) {
            g_rowptr[idx] = run;
            float degf = (float)cc[k] + 1e-9f;
            g_dinv[idx] = rsqrtf(degf);
            g_dpos[idx] = sqrtf(degf);
            if (cc[k] & 1) g_ecol[run + cc[k]] = N_TOTAL;   // pad -> zero row
            run += cp[k];
        }
    }
}

// X0 = fp16(d_inv[node] * E0)   (runs after scan; 8 floats per thread)
__global__ void k_prep(const float4* __restrict__ E0) {
    int i = blockIdx.x * blockDim.x + threadIdx.x;
    const int n8 = N_TOTAL * DIM / 8;
    if (i >= n8) return;
    float dv = __ldg(g_dinv + (i >> 3));          // 8 threads per node row
    float4 f0 = __ldg(E0 + i * 2);
    float4 f1 = __ldg(E0 + i * 2 + 1);
    uint4 h;
    h.x = h22u(__floats2half2_rn(dv * f0.x, dv * f0.y));
    h.y = h22u(__floats2half2_rn(dv * f0.z, dv * f0.w));
    h.z = h22u(__floats2half2_rn(dv * f1.x, dv * f1.y));
    h.w = h22u(__floats2half2_rn(dv * f1.z, dv * f1.w));
    reinterpret_cast<uint4*>(g_X0)[i] = h;
}

// scatter column indices into CSR slots — atomic-free, 4B stores.
__global__ void k_scatter(const int* __restrict__ row, const int* __restrict__ col,
                          int nnz) {
    int t = blockIdx.x * blockDim.x + threadIdx.x;
    int base = t * 4;
    if (base + 4 <= nnz) {
        int4 r = __ldg(reinterpret_cast<const int4*>(row + base));
        int4 c = __ldg(reinterpret_cast<const int4*>(col + base));
        int4 k = *reinterpret_cast<const int4*>(g_rank + base);
        g_ecol[__ldg(g_rowptr + r.x) + k.x] = c.x;
        g_ecol[__ldg(g_rowptr + r.y) + k.y] = c.y;
        g_ecol[__ldg(g_rowptr + r.z) + k.z] = c.z;
        g_ecol[__ldg(g_rowptr + r.w) + k.w] = c.w;
    } else {
        for (int e = base; e < nnz; e++) {
            int rr = __ldg(row + e);
            g_ecol[__ldg(g_rowptr + rr) + g_rank[e]] = __ldg(col + e);
        }
    }
}

// ---------------------------------------------------------------------------
// accumulate uint4 (8 halfs) into float2[4] — pure adds
__device__ __forceinline__ void add_h8(float2 acc[4], uint4 h) {
    float2 p;
    p = __half22float2(u2h2(h.x)); acc[0].x += p.x; acc[0].y += p.y;
    p = __half22float2(u2h2(h.y)); acc[1].x += p.x; acc[1].y += p.y;
    p = __half22float2(u2h2(h.z)); acc[2].x += p.x; acc[2].y += p.y;
    p = __half22float2(u2h2(h.w)); acc[3].x += p.x; acc[3].y += p.y;
}

// scaled-space SpMM: dst[r] = d_inv[r]^2 * sum_{c in N(r)} src[c]
// 8 threads/row, 8 dims/lane, pure gather+add inner loop.
__global__ void k_spmm(const __half* __restrict__ src, __half* __restrict__ dst) {
    int t = blockIdx.x * blockDim.x + threadIdx.x;
    int r = t >> 3;
    int q = t & 7;
    if (r >= N_TOTAL) return;

    int beg = __ldg(g_rowptr + r);
    int cnt2 = (__ldg(g_cnt + r) + 1) & ~1;     // padded (pad cols hit zero row)
    const int* cp = g_ecol + beg;               // beg is even -> 8B aligned
    const uint4* src4 = reinterpret_cast<const uint4*>(src);

    float2 a0[4] = {{0,0},{0,0},{0,0},{0,0}};
    float2 a1[4] = {{0,0},{0,0},{0,0},{0,0}};

    int i = 0;
    for (; i + 4 <= cnt2; i += 4) {
        int2 c01 = *reinterpret_cast<const int2*>(cp + i);
        int2 c23 = *reinterpret_cast<const int2*>(cp + i + 2);
        uint4 h0 = __ldg(src4 + (c01.x * 8 + q));
        uint4 h1 = __ldg(src4 + (c01.y * 8 + q));
        uint4 h2 = __ldg(src4 + (c23.x * 8 + q));
        uint4 h3 = __ldg(src4 + (c23.y * 8 + q));
        add_h8(a0, h0);
        add_h8(a1, h1);
        add_h8(a0, h2);
        add_h8(a1, h3);
    }
    if (i < cnt2) {
        int2 c01 = *reinterpret_cast<const int2*>(cp + i);
        uint4 h0 = __ldg(src4 + (c01.x * 8 + q));
        uint4 h1 = __ldg(src4 + (c01.y * 8 + q));
        add_h8(a0, h0);
        add_h8(a1, h1);
    }

    float dv = __ldg(g_dinv + r);
    float s = dv * dv;
    uint4 o;
    o.x = h22u(__floats2half2_rn((a0[0].x + a1[0].x) * s, (a0[0].y + a1[0].y) * s));
    o.y = h22u(__floats2half2_rn((a0[1].x + a1[1].x) * s, (a0[1].y + a1[1].y) * s));
    o.z = h22u(__floats2half2_rn((a0[2].x + a1[2].x) * s, (a0[2].y + a1[2].y) * s));
    o.w = h22u(__floats2half2_rn((a0[3].x + a1[3].x) * s, (a0[3].y + a1[3].y) * s));
    reinterpret_cast<uint4*>(dst)[r * 8 + q] = o;
}

// ---------------------------------------------------------------------------
// Fused layer-3 + output. For each gathered node:
//   sum3 = sum_{c in N(node)} XB[c]          (scaled-space layer-3 gather)
//   final = (E0 + (XA+XB)[node]*dpos + dinv*sum3) / 4 ;  also emit E0.
__global__ void k_out(const int* __restrict__ users, const int* __restrict__ pos,
                      const int* __restrict__ neg, const float* __restrict__ E0,
                      float* __restrict__ out) {
    int t = blockIdx.x * blockDim.x + threadIdx.x;
    if (t >= 3 * BATCH * 8) return;
    int s = t >> 15;            // BATCH*8 = 32768
    int rem = t & 32767;
    int b = rem >> 3;
    int q = rem & 7;

    int node;
    if (s == 0)      node = __ldg(users + b);
    else if (s == 1) node = N_USERS + __ldg(pos + b);
    else             node = N_USERS + __ldg(neg + b);

    int beg = __ldg(g_rowptr + node);
    int cnt2 = (__ldg(g_cnt + node) + 1) & ~1;
    const int* cp = g_ecol + beg;
    const uint4* B4 = reinterpret_cast<const uint4*>(g_XB);

    float2 c0[4] = {{0,0},{0,0},{0,0},{0,0}};
    for (int i = 0; i < cnt2; i += 2) {
        int2 c01 = *reinterpret_cast<const int2*>(cp + i);
        uint4 h0 = __ldg(B4 + (c01.x * 8 + q));
        uint4 h1 = __ldg(B4 + (c01.y * 8 + q));
        add_h8(c0, h0);
        add_h8(c0, h1);
    }

    float dv = __ldg(g_dinv + node);
    float dp = __ldg(g_dpos + node);

    int off4 = node * 8 + q;
    uint4 ha = __ldg(reinterpret_cast<const uint4*>(g_XA) + off4);
    uint4 hb = __ldg(B4 + off4);
    size_t offf = (size_t)node * DIM + q * 8;
    float4 e00 = __ldg(reinterpret_cast<const float4*>(E0 + offf));
    float4 e01v = __ldg(reinterpret_cast<const float4*>(E0 + offf + 4));

    float2 pa, pb;
    float outv[8];
    pa = __half22float2(u2h2(ha.x)); pb = __half22float2(u2h2(hb.x));
    outv[0] = (e00.x + (pa.x + pb.x) * dp + dv * c0[0].x) * 0.25f;
    outv[1] = (e00.y + (pa.y + pb.y) * dp + dv * c0[0].y) * 0.25f;
    pa = __half22float2(u2h2(ha.y)); pb = __half22float2(u2h2(hb.y));
    outv[2] = (e00.z + (pa.x + pb.x) * dp + dv * c0[1].x) * 0.25f;
    outv[3] = (e00.w + (pa.y + pb.y) * dp + dv * c0[1].y) * 0.25f;
    pa = __half22float2(u2h2(ha.z)); pb = __half22float2(u2h2(hb.z));
    outv[4] = (e01v.x + (pa.x + pb.x) * dp + dv * c0[2].x) * 0.25f;
    outv[5] = (e01v.y + (pa.y + pb.y) * dp + dv * c0[2].y) * 0.25f;
    pa = __half22float2(u2h2(ha.w)); pb = __half22float2(u2h2(hb.w));
    outv[6] = (e01v.z + (pa.x + pb.x) * dp + dv * c0[3].x) * 0.25f;
    outv[7] = (e01v.w + (pa.y + pb.y) * dp + dv * c0[3].y) * 0.25f;

    const int S = BATCH * DIM;
    int o = b * DIM + q * 8;
    float4* op = reinterpret_cast<float4*>(out + (size_t)s * S + o);
    op[0] = make_float4(outv[0], outv[1], outv[2], outv[3]);
    op[1] = make_float4(outv[4], outv[5], outv[6], outv[7]);
    float4* oe = reinterpret_cast<float4*>(out + (size_t)(s + 3) * S + o);
    oe[0] = e00;
    oe[1] = e01v;
}

extern "C" void kernel_launch(void* const* d_in, const int* in_sizes, int n_in,
                              void* d_out, int out_size) {
    const int*   users = (const int*)d_in[0];
    const int*   pos   = (const int*)d_in[1];
    const int*   neg   = (const int*)d_in[2];
    const float* E0    = (const float*)d_in[3];
    const int*   row   = (const int*)d_in[4];
    const int*   col   = (const int*)d_in[5];
    const int    nnz   = in_sizes[4];

    __half *X0, *XA, *XB;
    cudaGetSymbolAddress((void**)&X0, g_X0);
    cudaGetSymbolAddress((void**)&XA, g_XA);
    cudaGetSymbolAddress((void**)&XB, g_XB);

    const int TB = 256;

    // CSR build + normalizers
    k_zero<<<(N_TOTAL / 4 + TB - 1) / TB, TB>>>();
    int quads = (nnz + 3) / 4;
    k_hist<<<(quads + TB - 1) / TB, TB>>>(row, nnz);
    k_scan<<<NB, 1024>>>();
    const int n8 = N_TOTAL * DIM / 8;
    k_prep<<<(n8 + TB - 1) / TB, TB>>>((const float4*)E0);
    k_scatter<<<(quads + TB - 1) / TB, TB>>>(row, col, nnz);

    // 2 scaled-space propagation layers
    const int spmmGrid = (N_TOTAL * 8 + TB - 1) / TB;
    k_spmm<<<spmmGrid, TB>>>(X0, XA);   // XA = Dinv2 * (A @ X0)
    k_spmm<<<spmmGrid, TB>>>(XA, XB);   // XB = Dinv2 * (A @ XA)

    // fused layer 3 + gather
    int outThreads = 3 * BATCH * 8;
    k_out<<<(outThreads + TB - 1) / TB, TB>>>(users, pos, neg, E0, (float*)d_out);
}

// round 9
// speedup vs baseline: 2.6702x; 1.0375x over previous
#include <cuda_runtime.h>
#include <cuda_fp16.h>

#define N_USERS  100000
#define N_TOTAL  150000
#define DIM      64
#define BATCH    4096
#define NNZ_MAX  1400000     // 1.2M edges + up to 150k pad slots

#define SCAN_TILE 4096                                  // 1024 threads x 4 items
#define NB ((N_TOTAL + SCAN_TILE - 1) / SCAN_TILE)      // 37 blocks (all resident)

// Scaled-space embeddings X_k = d_inv ⊙ E_k, fp16, with one extra zero row
// (index N_TOTAL) used as the gather target of pad edges.
__device__ __half g_X0[(N_TOTAL + 1) * DIM];
__device__ __half g_XA[(N_TOTAL + 1) * DIM];
__device__ __half g_XB[(N_TOTAL + 1) * DIM];
__device__ float g_dinv[N_TOTAL];        // (deg+1e-9)^-0.5
__device__ float g_dpos[N_TOTAL];        // (deg+1e-9)^+0.5  (to unscale)
__device__ int   g_cnt[N_TOTAL];         // true row degree
__device__ int   g_rowptr[N_TOTAL];      // padded-to-even exclusive scan
__device__ int   g_rank[NNZ_MAX];        // intra-row rank per edge (from hist)
__device__ int   g_ecol[NNZ_MAX];        // CSR column indices; pad slots = N_TOTAL
__device__ int   g_blockAgg[64];
__device__ int   g_aggReady[64];

__device__ __forceinline__ __half2 u2h2(unsigned u) {
    __half2 h; *reinterpret_cast<unsigned*>(&h) = u; return h;
}
__device__ __forceinline__ unsigned h22u(__half2 h) {
    return *reinterpret_cast<unsigned*>(&h);
}

// ---------------------------------------------------------------------------
// zero counters, scan flags, and the sentinel rows of X0/XA/XB
__global__ void k_zero() {
    int i = blockIdx.x * blockDim.x + threadIdx.x;
    if (i < N_TOTAL / 4) reinterpret_cast<int4*>(g_cnt)[i] = make_int4(0, 0, 0, 0);
    if (i < 64) { g_aggReady[i] = 0; g_blockAgg[i] = 0; }
    if (i < 8) {
        uint4 z = make_uint4(0, 0, 0, 0);
        reinterpret_cast<uint4*>(g_X0 + N_TOTAL * DIM)[i] = z;
        reinterpret_cast<uint4*>(g_XA + N_TOTAL * DIM)[i] = z;
        reinterpret_cast<uint4*>(g_XB + N_TOTAL * DIM)[i] = z;
    }
}

// histogram of row ids, capturing each edge's intra-row rank (4 edges/thread)
__global__ void k_hist(const int* __restrict__ row, int nnz) {
    int t = blockIdx.x * blockDim.x + threadIdx.x;
    int base = t * 4;
    if (base + 4 <= nnz) {
        int4 r = __ldg(reinterpret_cast<const int4*>(row + base));
        int4 k;
        k.x = atomicAdd(&g_cnt[r.x], 1);
        k.y = atomicAdd(&g_cnt[r.y], 1);
        k.z = atomicAdd(&g_cnt[r.z], 1);
        k.w = atomicAdd(&g_cnt[r.w], 1);
        *reinterpret_cast<int4*>(g_rank + base) = k;
    } else {
        for (int e = base; e < nnz; e++)
            g_rank[e] = atomicAdd(&g_cnt[__ldg(row + e)], 1);
    }
}

// single-pass exclusive scan of padded counts -> rowptr; also derives the
// degree normalizers and writes pad-edge sentinels for odd-degree rows.
__global__ void k_scan() {
    __shared__ int warpsum[32];
    __shared__ int s_aggs[64];
    __shared__ int s_prev;
    int tid  = threadIdx.x;
    int lane = tid & 31, wid = tid >> 5;
    int base = blockIdx.x * SCAN_TILE + tid * 4;

    int cc[4], cp[4];
#pragma unroll
    for (int k = 0; k < 4; k++) {
        int idx = base + k;
        cc[k] = (idx < N_TOTAL) ? g_cnt[idx] : 0;
        cp[k] = (cc[k] + 1) & ~1;                 // padded to even
    }
    int t = cp[0] + cp[1] + cp[2] + cp[3];

    int x = t;
#pragma unroll
    for (int o = 1; o < 32; o <<= 1) {
        int y = __shfl_up_sync(0xffffffffu, x, o);
        if (lane >= o) x += y;
    }
    if (lane == 31) warpsum[wid] = x;
    __syncthreads();
    if (wid == 0) {
        int v = warpsum[lane];
#pragma unroll
        for (int o = 1; o < 32; o <<= 1) {
            int y = __shfl_up_sync(0xffffffffu, v, o);
            if (lane >= o) v += y;
        }
        warpsum[lane] = v;
    }
    __syncthreads();

    if (tid == 0) {
        g_blockAgg[blockIdx.x] = warpsum[31];
        __threadfence();
        atomicExch(&g_aggReady[blockIdx.x], 1);
    }
    if (tid < blockIdx.x) {
        while (atomicAdd(&g_aggReady[tid], 0) == 0) { }
        __threadfence();
        s_aggs[tid] = g_blockAgg[tid];
    }
    __syncthreads();
    if (tid == 0) {
        int p = 0;
        for (int j = 0; j < blockIdx.x; j++) p += s_aggs[j];
        s_prev = p;
    }
    __syncthreads();

    int woff = (wid == 0) ? 0 : warpsum[wid - 1];
    int run = s_prev + woff + (x - t);
#pragma unroll
    for (int k = 0; k < 4; k++) {
        int idx = base + k;
        if (idx < N_TOTAL) {
            g_rowptr[idx] = run;
            float degf = (float)cc[k] + 1e-9f;
            g_dinv[idx] = rsqrtf(degf);
            g_dpos[idx] = sqrtf(degf);
            if (cc[k] & 1) g_ecol[run + cc[k]] = N_TOTAL;   // pad -> zero row
            run += cp[k];
        }
    }
}

// ---------------------------------------------------------------------------
// Fused prep + scatter (independent stages, complementary bottlenecks:
// prep is DRAM-stream-bound, scatter is L2-latency-bound — co-resident blocks
// overlap them on the SM array without streams).
//   blocks [0, scatterBlocks)                : CSR column scatter (atomic-free)
//   blocks [scatterBlocks, +prepBlocks)      : X0 = fp16(d_inv * E0)
__global__ void k_prep_scatter(const float4* __restrict__ E0,
                               const int* __restrict__ row,
                               const int* __restrict__ col,
                               int nnz, int scatterBlocks) {
    if (blockIdx.x < (unsigned)scatterBlocks) {
        // ---- scatter: 4 edges/thread, slot = rowptr[row] + rank[edge]
        int t = blockIdx.x * blockDim.x + threadIdx.x;
        int base = t * 4;
        if (base + 4 <= nnz) {
            int4 r = __ldg(reinterpret_cast<const int4*>(row + base));
            int4 c = __ldg(reinterpret_cast<const int4*>(col + base));
            int4 k = *reinterpret_cast<const int4*>(g_rank + base);
            g_ecol[__ldg(g_rowptr + r.x) + k.x] = c.x;
            g_ecol[__ldg(g_rowptr + r.y) + k.y] = c.y;
            g_ecol[__ldg(g_rowptr + r.z) + k.z] = c.z;
            g_ecol[__ldg(g_rowptr + r.w) + k.w] = c.w;
        } else {
            for (int e = base; e < nnz; e++) {
                int rr = __ldg(row + e);
                g_ecol[__ldg(g_rowptr + rr) + g_rank[e]] = __ldg(col + e);
            }
        }
    } else {
        // ---- prep: X0 = fp16(d_inv[node] * E0), 8 floats per thread
        int i = (blockIdx.x - scatterBlocks) * blockDim.x + threadIdx.x;
        const int n8 = N_TOTAL * DIM / 8;
        if (i >= n8) return;
        float dv = __ldg(g_dinv + (i >> 3));          // 8 threads per node row
        float4 f0 = __ldg(E0 + i * 2);
        float4 f1 = __ldg(E0 + i * 2 + 1);
        uint4 h;
        h.x = h22u(__floats2half2_rn(dv * f0.x, dv * f0.y));
        h.y = h22u(__floats2half2_rn(dv * f0.z, dv * f0.w));
        h.z = h22u(__floats2half2_rn(dv * f1.x, dv * f1.y));
        h.w = h22u(__floats2half2_rn(dv * f1.z, dv * f1.w));
        reinterpret_cast<uint4*>(g_X0)[i] = h;
    }
}

// ---------------------------------------------------------------------------
// accumulate uint4 (8 halfs) into float2[4] — pure adds
__device__ __forceinline__ void add_h8(float2 acc[4], uint4 h) {
    float2 p;
    p = __half22float2(u2h2(h.x)); acc[0].x += p.x; acc[0].y += p.y;
    p = __half22float2(u2h2(h.y)); acc[1].x += p.x; acc[1].y += p.y;
    p = __half22float2(u2h2(h.z)); acc[2].x += p.x; acc[2].y += p.y;
    p = __half22float2(u2h2(h.w)); acc[3].x += p.x; acc[3].y += p.y;
}

// scaled-space SpMM: dst[r] = d_inv[r]^2 * sum_{c in N(r)} src[c]
// 8 threads/row, 8 dims/lane, pure gather+add inner loop.
__global__ void k_spmm(const __half* __restrict__ src, __half* __restrict__ dst) {
    int t = blockIdx.x * blockDim.x + threadIdx.x;
    int r = t >> 3;
    int q = t & 7;
    if (r >= N_TOTAL) return;

    int beg = __ldg(g_rowptr + r);
    int cnt2 = (__ldg(g_cnt + r) + 1) & ~1;     // padded (pad cols hit zero row)
    const int* cp = g_ecol + beg;               // beg is even -> 8B aligned
    const uint4* src4 = reinterpret_cast<const uint4*>(src);

    float2 a0[4] = {{0,0},{0,0},{0,0},{0,0}};
    float2 a1[4] = {{0,0},{0,0},{0,0},{0,0}};

    int i = 0;
    for (; i + 4 <= cnt2; i += 4) {
        int2 c01 = *reinterpret_cast<const int2*>(cp + i);
        int2 c23 = *reinterpret_cast<const int2*>(cp + i + 2);
        uint4 h0 = __ldg(src4 + (c01.x * 8 + q));
        uint4 h1 = __ldg(src4 + (c01.y * 8 + q));
        uint4 h2 = __ldg(src4 + (c23.x * 8 + q));
        uint4 h3 = __ldg(src4 + (c23.y * 8 + q));
        add_h8(a0, h0);
        add_h8(a1, h1);
        add_h8(a0, h2);
        add_h8(a1, h3);
    }
    if (i < cnt2) {
        int2 c01 = *reinterpret_cast<const int2*>(cp + i);
        uint4 h0 = __ldg(src4 + (c01.x * 8 + q));
        uint4 h1 = __ldg(src4 + (c01.y * 8 + q));
        add_h8(a0, h0);
        add_h8(a1, h1);
    }

    float dv = __ldg(g_dinv + r);
    float s = dv * dv;
    uint4 o;
    o.x = h22u(__floats2half2_rn((a0[0].x + a1[0].x) * s, (a0[0].y + a1[0].y) * s));
    o.y = h22u(__floats2half2_rn((a0[1].x + a1[1].x) * s, (a0[1].y + a1[1].y) * s));
    o.z = h22u(__floats2half2_rn((a0[2].x + a1[2].x) * s, (a0[2].y + a1[2].y) * s));
    o.w = h22u(__floats2half2_rn((a0[3].x + a1[3].x) * s, (a0[3].y + a1[3].y) * s));
    reinterpret_cast<uint4*>(dst)[r * 8 + q] = o;
}

// ---------------------------------------------------------------------------
// Fused layer-3 + output. For each gathered node:
//   sum3 = sum_{c in N(node)} XB[c]          (scaled-space layer-3 gather)
//   final = (E0 + (XA+XB)[node]*dpos + dinv*sum3) / 4 ;  also emit E0.
__global__ void k_out(const int* __restrict__ users, const int* __restrict__ pos,
                      const int* __restrict__ neg, const float* __restrict__ E0,
                      float* __restrict__ out) {
    int t = blockIdx.x * blockDim.x + threadIdx.x;
    if (t >= 3 * BATCH * 8) return;
    int s = t >> 15;            // BATCH*8 = 32768
    int rem = t & 32767;
    int b = rem >> 3;
    int q = rem & 7;

    int node;
    if (s == 0)      node = __ldg(users + b);
    else if (s == 1) node = N_USERS + __ldg(pos + b);
    else             node = N_USERS + __ldg(neg + b);

    int beg = __ldg(g_rowptr + node);
    int cnt2 = (__ldg(g_cnt + node) + 1) & ~1;
    const int* cp = g_ecol + beg;
    const uint4* B4 = reinterpret_cast<const uint4*>(g_XB);

    float2 c0[4] = {{0,0},{0,0},{0,0},{0,0}};
    for (int i = 0; i < cnt2; i += 2) {
        int2 c01 = *reinterpret_cast<const int2*>(cp + i);
        uint4 h0 = __ldg(B4 + (c01.x * 8 + q));
        uint4 h1 = __ldg(B4 + (c01.y * 8 + q));
        add_h8(c0, h0);
        add_h8(c0, h1);
    }

    float dv = __ldg(g_dinv + node);
    float dp = __ldg(g_dpos + node);

    int off4 = node * 8 + q;
    uint4 ha = __ldg(reinterpret_cast<const uint4*>(g_XA) + off4);
    uint4 hb = __ldg(B4 + off4);
    size_t offf = (size_t)node * DIM + q * 8;
    float4 e00 = __ldg(reinterpret_cast<const float4*>(E0 + offf));
    float4 e01v = __ldg(reinterpret_cast<const float4*>(E0 + offf + 4));

    float2 pa, pb;
    float outv[8];
    pa = __half22float2(u2h2(ha.x)); pb = __half22float2(u2h2(hb.x));
    outv[0] = (e00.x + (pa.x + pb.x) * dp + dv * c0[0].x) * 0.25f;
    outv[1] = (e00.y + (pa.y + pb.y) * dp + dv * c0[0].y) * 0.25f;
    pa = __half22float2(u2h2(ha.y)); pb = __half22float2(u2h2(hb.y));
    outv[2] = (e00.z + (pa.x + pb.x) * dp + dv * c0[1].x) * 0.25f;
    outv[3] = (e00.w + (pa.y + pb.y) * dp + dv * c0[1].y) * 0.25f;
    pa = __half22float2(u2h2(ha.z)); pb = __half22float2(u2h2(hb.z));
    outv[4] = (e01v.x + (pa.x + pb.x) * dp + dv * c0[2].x) * 0.25f;
    outv[5] = (e01v.y + (pa.y + pb.y) * dp + dv * c0[2].y) * 0.25f;
    pa = __half22float2(u2h2(ha.w)); pb = __half22float2(u2h2(hb.w));
    outv[6] = (e01v.z + (pa.x + pb.x) * dp + dv * c0[3].x) * 0.25f;
    outv[7] = (e01v.w + (pa.y + pb.y) * dp + dv * c0[3].y) * 0.25f;

    const int S = BATCH * DIM;
    int o = b * DIM + q * 8;
    float4* op = reinterpret_cast<float4*>(out + (size_t)s * S + o);
    op[0] = make_float4(outv[0], outv[1], outv[2], outv[3]);
    op[1] = make_float4(outv[4], outv[5], outv[6], outv[7]);
    float4* oe = reinterpret_cast<float4*>(out + (size_t)(s + 3) * S + o);
    oe[0] = e00;
    oe[1] = e01v;
}

extern "C" void kernel_launch(void* const* d_in, const int* in_sizes, int n_in,
                              void* d_out, int out_size) {
    const int*   users = (const int*)d_in[0];
    const int*   pos   = (const int*)d_in[1];
    const int*   neg   = (const int*)d_in[2];
    const float* E0    = (const float*)d_in[3];
    const int*   row   = (const int*)d_in[4];
    const int*   col   = (const int*)d_in[5];
    const int    nnz   = in_sizes[4];

    __half *X0, *XA, *XB;
    cudaGetSymbolAddress((void**)&X0, g_X0);
    cudaGetSymbolAddress((void**)&XA, g_XA);
    cudaGetSymbolAddress((void**)&XB, g_XB);

    const int TB = 256;

    // CSR build + normalizers
    k_zero<<<(N_TOTAL / 4 + TB - 1) / TB, TB>>>();
    int quads = (nnz + 3) / 4;
    k_hist<<<(quads + TB - 1) / TB, TB>>>(row, nnz);
    k_scan<<<NB, 1024>>>();

    // fused prep + scatter (independent post-scan stages, overlapped)
    const int n8 = N_TOTAL * DIM / 8;
    int scatterBlocks = (quads + TB - 1) / TB;
    int prepBlocks = (n8 + TB - 1) / TB;
    k_prep_scatter<<<scatterBlocks + prepBlocks, TB>>>(
        (const float4*)E0, row, col, nnz, scatterBlocks);

    // 2 scaled-space propagation layers
    const int spmmGrid = (N_TOTAL * 8 + TB - 1) / TB;
    k_spmm<<<spmmGrid, TB>>>(X0, XA);   // XA = Dinv2 * (A @ X0)
    k_spmm<<<spmmGrid, TB>>>(XA, XB);   // XB = Dinv2 * (A @ XA)

    // fused layer 3 + gather
    int outThreads = 3 * BATCH * 8;
    k_out<<<(outThreads + TB - 1) / TB, TB>>>(users, pos, neg, E0, (float*)d_out);
}

// round 10
// speedup vs baseline: 2.7794x; 1.0409x over previous
#include <cuda_runtime.h>
#include <cuda_fp16.h>

#define N_USERS  100000
#define N_TOTAL  150000
#define DIM      64
#define BATCH    4096
#define NNZ_MAX  1400000     // 1.2M edges + up to 150k pad slots

#define SCAN_TILE 4096                                  // 1024 threads x 4 items
#define NB ((N_TOTAL + SCAN_TILE - 1) / SCAN_TILE)      // 37 blocks (all resident)

// Scaled-space embeddings X_k = d_inv ⊙ E_k, fp16, with one extra zero row
// (index N_TOTAL) used as the gather target of pad edges. All __device__
// globals are zero-initialized at module load; the sentinel rows are never
// written, so they stay zero. g_cnt and the scan flags are re-zeroed each call
// by the aux lane of k_prep_scatter (for the NEXT call).
__device__ __half g_X0[(N_TOTAL + 1) * DIM];
__device__ __half g_XA[(N_TOTAL + 1) * DIM];
__device__ __half g_XB[(N_TOTAL + 1) * DIM];
__device__ float g_dinv[N_TOTAL];        // (deg+1e-9)^-0.5
__device__ float g_dpos[N_TOTAL];        // (deg+1e-9)^+0.5  (to unscale)
__device__ int   g_cnt[N_TOTAL];         // true row degree (zeroed for next call)
__device__ int   g_rowptr[N_TOTAL + 1];  // padded exclusive scan (+ total at end)
__device__ int   g_rank[NNZ_MAX];        // intra-row rank per edge (from hist)
__device__ int   g_ecol[NNZ_MAX];        // CSR column indices; pad slots = N_TOTAL
__device__ int   g_blockAgg[64];
__device__ int   g_aggReady[64];

__device__ __forceinline__ __half2 u2h2(unsigned u) {
    __half2 h; *reinterpret_cast<unsigned*>(&h) = u; return h;
}
__device__ __forceinline__ unsigned h22u(__half2 h) {
    return *reinterpret_cast<unsigned*>(&h);
}

// ---------------------------------------------------------------------------
// histogram of row ids, capturing each edge's intra-row rank (4 edges/thread)
__global__ void k_hist(const int* __restrict__ row, int nnz) {
    int t = blockIdx.x * blockDim.x + threadIdx.x;
    int base = t * 4;
    if (base + 4 <= nnz) {
        int4 r = __ldg(reinterpret_cast<const int4*>(row + base));
        int4 k;
        k.x = atomicAdd(&g_cnt[r.x], 1);
        k.y = atomicAdd(&g_cnt[r.y], 1);
        k.z = atomicAdd(&g_cnt[r.z], 1);
        k.w = atomicAdd(&g_cnt[r.w], 1);
        *reinterpret_cast<int4*>(g_rank + base) = k;
    } else {
        for (int e = base; e < nnz; e++)
            g_rank[e] = atomicAdd(&g_cnt[__ldg(row + e)], 1);
    }
}

// single-pass exclusive scan of padded counts -> rowptr (incl. total at
// rowptr[N_TOTAL]); derives degree normalizers; writes pad-edge sentinels.
__global__ void k_scan() {
    __shared__ int warpsum[32];
    __shared__ int s_aggs[64];
    __shared__ int s_prev;
    int tid  = threadIdx.x;
    int lane = tid & 31, wid = tid >> 5;
    int base = blockIdx.x * SCAN_TILE + tid * 4;

    int cc[4], cp[4];
#pragma unroll
    for (int k = 0; k < 4; k++) {
        int idx = base + k;
        cc[k] = (idx < N_TOTAL) ? g_cnt[idx] : 0;
        cp[k] = (cc[k] + 1) & ~1;                 // padded to even
    }
    int t = cp[0] + cp[1] + cp[2] + cp[3];

    int x = t;
#pragma unroll
    for (int o = 1; o < 32; o <<= 1) {
        int y = __shfl_up_sync(0xffffffffu, x, o);
        if (lane >= o) x += y;
    }
    if (lane == 31) warpsum[wid] = x;
    __syncthreads();
    if (wid == 0) {
        int v = warpsum[lane];
#pragma unroll
        for (int o = 1; o < 32; o <<= 1) {
            int y = __shfl_up_sync(0xffffffffu, v, o);
            if (lane >= o) v += y;
        }
        warpsum[lane] = v;
    }
    __syncthreads();

    if (tid == 0) {
        g_blockAgg[blockIdx.x] = warpsum[31];
        __threadfence();
        atomicExch(&g_aggReady[blockIdx.x], 1);
    }
    if (tid < blockIdx.x) {
        while (atomicAdd(&g_aggReady[tid], 0) == 0) { }
        __threadfence();
        s_aggs[tid] = g_blockAgg[tid];
    }
    __syncthreads();
    if (tid == 0) {
        int p = 0;
        for (int j = 0; j < blockIdx.x; j++) p += s_aggs[j];
        s_prev = p;
    }
    __syncthreads();

    int woff = (wid == 0) ? 0 : warpsum[wid - 1];
    int run = s_prev + woff + (x - t);
#pragma unroll
    for (int k = 0; k < 4; k++) {
        int idx = base + k;
        if (idx < N_TOTAL) {
            g_rowptr[idx] = run;
            float degf = (float)cc[k] + 1e-9f;
            g_dinv[idx] = rsqrtf(degf);
            g_dpos[idx] = sqrtf(degf);
            if (cc[k] & 1) g_ecol[run + cc[k]] = N_TOTAL;   // pad -> zero row
            run += cp[k];
            if (idx == N_TOTAL - 1) g_rowptr[N_TOTAL] = run;  // total
        }
    }
}

// ---------------------------------------------------------------------------
// Fused scatter + prep + counter-rezero, with blocks INTERLEAVED by modulo so
// every scheduling wave mixes L2-latency-bound scatter blocks with
// DRAM-streaming prep blocks (contiguous partitioning degenerated to serial
// execution because scatter's block count equals one wave).
//   (blockIdx & 3) == 0 : aux lane -> scatter blocks, then zeroing blocks
//   else                : prep lane -> X0 = fp16(d_inv * E0)
__global__ void k_prep_scatter(const float4* __restrict__ E0,
                               const int* __restrict__ row,
                               const int* __restrict__ col,
                               int nnz, int sBlocks, int zBlocks, int pBlocks) {
    unsigned b = blockIdx.x;
    if ((b & 3u) == 0u) {
        int aux = b >> 2;
        if (aux < sBlocks) {
            // ---- scatter: 4 edges/thread, slot = rowptr[row] + rank[edge]
            int t = aux * blockDim.x + threadIdx.x;
            int base = t * 4;
            if (base + 4 <= nnz) {
                int4 r = __ldg(reinterpret_cast<const int4*>(row + base));
                int4 c = __ldg(reinterpret_cast<const int4*>(col + base));
                int4 k = *reinterpret_cast<const int4*>(g_rank + base);
                g_ecol[__ldg(g_rowptr + r.x) + k.x] = c.x;
                g_ecol[__ldg(g_rowptr + r.y) + k.y] = c.y;
                g_ecol[__ldg(g_rowptr + r.z) + k.z] = c.z;
                g_ecol[__ldg(g_rowptr + r.w) + k.w] = c.w;
            } else {
                for (int e = base; e < nnz; e++) {
                    int rr = __ldg(row + e);
                    g_ecol[__ldg(g_rowptr + rr) + g_rank[e]] = __ldg(col + e);
                }
            }
        } else if (aux < sBlocks + zBlocks) {
            // ---- zero g_cnt + scan flags for the NEXT call (safe: nothing
            // after k_scan reads them in this call)
            int zb = aux - sBlocks;
            int i = zb * blockDim.x + threadIdx.x;
            if (i < N_TOTAL / 4)
                reinterpret_cast<int4*>(g_cnt)[i] = make_int4(0, 0, 0, 0);
            if (zb == 0 && threadIdx.x < 16) {
                reinterpret_cast<int4*>(g_aggReady)[threadIdx.x] = make_int4(0, 0, 0, 0);
                reinterpret_cast<int4*>(g_blockAgg)[threadIdx.x] = make_int4(0, 0, 0, 0);
            }
        }
    } else {
        // ---- prep: X0 = fp16(d_inv[node] * E0), 8 floats per thread
        int pb = (int)b - (int)(b >> 2) - 1;     // rank among non-aux blocks
        if (pb >= pBlocks) return;
        int i = pb * blockDim.x + threadIdx.x;
        const int n8 = N_TOTAL * DIM / 8;
        if (i >= n8) return;
        float dv = __ldg(g_dinv + (i >> 3));     // 8 threads per node row
        float4 f0 = __ldg(E0 + i * 2);
        float4 f1 = __ldg(E0 + i * 2 + 1);
        uint4 h;
        h.x = h22u(__floats2half2_rn(dv * f0.x, dv * f0.y));
        h.y = h22u(__floats2half2_rn(dv * f0.z, dv * f0.w));
        h.z = h22u(__floats2half2_rn(dv * f1.x, dv * f1.y));
        h.w = h22u(__floats2half2_rn(dv * f1.z, dv * f1.w));
        reinterpret_cast<uint4*>(g_X0)[i] = h;
    }
}

// ---------------------------------------------------------------------------
// accumulate uint4 (8 halfs) into float2[4] — pure adds
__device__ __forceinline__ void add_h8(float2 acc[4], uint4 h) {
    float2 p;
    p = __half22float2(u2h2(h.x)); acc[0].x += p.x; acc[0].y += p.y;
    p = __half22float2(u2h2(h.y)); acc[1].x += p.x; acc[1].y += p.y;
    p = __half22float2(u2h2(h.z)); acc[2].x += p.x; acc[2].y += p.y;
    p = __half22float2(u2h2(h.w)); acc[3].x += p.x; acc[3].y += p.y;
}

// scaled-space SpMM: dst[r] = d_inv[r]^2 * sum_{c in N(r)} src[c]
// 8 threads/row, 8 dims/lane. Padded count comes from rowptr diff (pad edges
// gather the zero sentinel row).
__global__ void k_spmm(const __half* __restrict__ src, __half* __restrict__ dst) {
    int t = blockIdx.x * blockDim.x + threadIdx.x;
    int r = t >> 3;
    int q = t & 7;
    if (r >= N_TOTAL) return;

    int beg  = __ldg(g_rowptr + r);
    int cnt2 = __ldg(g_rowptr + r + 1) - beg;   // padded (even)
    const int* cp = g_ecol + beg;               // beg is even -> 8B aligned
    const uint4* src4 = reinterpret_cast<const uint4*>(src);

    float2 a0[4] = {{0,0},{0,0},{0,0},{0,0}};
    float2 a1[4] = {{0,0},{0,0},{0,0},{0,0}};

    int i = 0;
    for (; i + 4 <= cnt2; i += 4) {
        int2 c01 = *reinterpret_cast<const int2*>(cp + i);
        int2 c23 = *reinterpret_cast<const int2*>(cp + i + 2);
        uint4 h0 = __ldg(src4 + (c01.x * 8 + q));
        uint4 h1 = __ldg(src4 + (c01.y * 8 + q));
        uint4 h2 = __ldg(src4 + (c23.x * 8 + q));
        uint4 h3 = __ldg(src4 + (c23.y * 8 + q));
        add_h8(a0, h0);
        add_h8(a1, h1);
        add_h8(a0, h2);
        add_h8(a1, h3);
    }
    if (i < cnt2) {
        int2 c01 = *reinterpret_cast<const int2*>(cp + i);
        uint4 h0 = __ldg(src4 + (c01.x * 8 + q));
        uint4 h1 = __ldg(src4 + (c01.y * 8 + q));
        add_h8(a0, h0);
        add_h8(a1, h1);
    }

    float dv = __ldg(g_dinv + r);
    float s = dv * dv;
    uint4 o;
    o.x = h22u(__floats2half2_rn((a0[0].x + a1[0].x) * s, (a0[0].y + a1[0].y) * s));
    o.y = h22u(__floats2half2_rn((a0[1].x + a1[1].x) * s, (a0[1].y + a1[1].y) * s));
    o.z = h22u(__floats2half2_rn((a0[2].x + a1[2].x) * s, (a0[2].y + a1[2].y) * s));
    o.w = h22u(__floats2half2_rn((a0[3].x + a1[3].x) * s, (a0[3].y + a1[3].y) * s));
    reinterpret_cast<uint4*>(dst)[r * 8 + q] = o;
}

// ---------------------------------------------------------------------------
// Fused layer-3 + output. For each gathered node:
//   sum3 = sum_{c in N(node)} XB[c]          (scaled-space layer-3 gather)
//   final = (E0 + (XA+XB)[node]*dpos + dinv*sum3) / 4 ;  also emit E0.
__global__ void k_out(const int* __restrict__ users, const int* __restrict__ pos,
                      const int* __restrict__ neg, const float* __restrict__ E0,
                      float* __restrict__ out) {
    int t = blockIdx.x * blockDim.x + threadIdx.x;
    if (t >= 3 * BATCH * 8) return;
    int s = t >> 15;            // BATCH*8 = 32768
    int rem = t & 32767;
    int b = rem >> 3;
    int q = rem & 7;

    int node;
    if (s == 0)      node = __ldg(users + b);
    else if (s == 1) node = N_USERS + __ldg(pos + b);
    else             node = N_USERS + __ldg(neg + b);

    int beg  = __ldg(g_rowptr + node);
    int cnt2 = __ldg(g_rowptr + node + 1) - beg;
    const int* cp = g_ecol + beg;
    const uint4* B4 = reinterpret_cast<const uint4*>(g_XB);

    float2 c0[4] = {{0,0},{0,0},{0,0},{0,0}};
    for (int i = 0; i < cnt2; i += 2) {
        int2 c01 = *reinterpret_cast<const int2*>(cp + i);
        uint4 h0 = __ldg(B4 + (c01.x * 8 + q));
        uint4 h1 = __ldg(B4 + (c01.y * 8 + q));
        add_h8(c0, h0);
        add_h8(c0, h1);
    }

    float dv = __ldg(g_dinv + node);
    float dp = __ldg(g_dpos + node);

    int off4 = node * 8 + q;
    uint4 ha = __ldg(reinterpret_cast<const uint4*>(g_XA) + off4);
    uint4 hb = __ldg(B4 + off4);
    size_t offf = (size_t)node * DIM + q * 8;
    float4 e00 = __ldg(reinterpret_cast<const float4*>(E0 + offf));
    float4 e01v = __ldg(reinterpret_cast<const float4*>(E0 + offf + 4));

    float2 pa, pb;
    float outv[8];
    pa = __half22float2(u2h2(ha.x)); pb = __half22float2(u2h2(hb.x));
    outv[0] = (e00.x + (pa.x + pb.x) * dp + dv * c0[0].x) * 0.25f;
    outv[1] = (e00.y + (pa.y + pb.y) * dp + dv * c0[0].y) * 0.25f;
    pa = __half22float2(u2h2(ha.y)); pb = __half22float2(u2h2(hb.y));
    outv[2] = (e00.z + (pa.x + pb.x) * dp + dv * c0[1].x) * 0.25f;
    outv[3] = (e00.w + (pa.y + pb.y) * dp + dv * c0[1].y) * 0.25f;
    pa = __half22float2(u2h2(ha.z)); pb = __half22float2(u2h2(hb.z));
    outv[4] = (e01v.x + (pa.x + pb.x) * dp + dv * c0[2].x) * 0.25f;
    outv[5] = (e01v.y + (pa.y + pb.y) * dp + dv * c0[2].y) * 0.25f;
    pa = __half22float2(u2h2(ha.w)); pb = __half22float2(u2h2(hb.w));
    outv[6] = (e01v.z + (pa.x + pb.x) * dp + dv * c0[3].x) * 0.25f;
    outv[7] = (e01v.w + (pa.y + pb.y) * dp + dv * c0[3].y) * 0.25f;

    const int S = BATCH * DIM;
    int o = b * DIM + q * 8;
    float4* op = reinterpret_cast<float4*>(out + (size_t)s * S + o);
    op[0] = make_float4(outv[0], outv[1], outv[2], outv[3]);
    op[1] = make_float4(outv[4], outv[5], outv[6], outv[7]);
    float4* oe = reinterpret_cast<float4*>(out + (size_t)(s + 3) * S + o);
    oe[0] = e00;
    oe[1] = e01v;
}

extern "C" void kernel_launch(void* const* d_in, const int* in_sizes, int n_in,
                              void* d_out, int out_size) {
    const int*   users = (const int*)d_in[0];
    const int*   pos   = (const int*)d_in[1];
    const int*   neg   = (const int*)d_in[2];
    const float* E0    = (const float*)d_in[3];
    const int*   row   = (const int*)d_in[4];
    const int*   col   = (const int*)d_in[5];
    const int    nnz   = in_sizes[4];

    __half *X0, *XA, *XB;
    cudaGetSymbolAddress((void**)&X0, g_X0);
    cudaGetSymbolAddress((void**)&XA, g_XA);
    cudaGetSymbolAddress((void**)&XB, g_XB);

    const int TB = 256;

    // CSR build + normalizers (counters were zeroed by the previous call's
    // prep_scatter, or by static zero-init on the first call)
    int quads = (nnz + 3) / 4;
    k_hist<<<(quads + TB - 1) / TB, TB>>>(row, nnz);
    k_scan<<<NB, 1024>>>();

    // fused scatter + prep + re-zero, interleaved for intra-wave overlap
    const int n8 = N_TOTAL * DIM / 8;
    int sBlocks = (quads + TB - 1) / TB;
    int zBlocks = (N_TOTAL / 4 + TB - 1) / TB;
    int pBlocks = (n8 + TB - 1) / TB;
    int auxBlocks = sBlocks + zBlocks;
    int total = (pBlocks * 4 + 2) / 3;          // prep needs 3/4 of the grid
    if (total < auxBlocks * 4) total = auxBlocks * 4;
    total = (total + 3) & ~3;
    k_prep_scatter<<<total, TB>>>((const float4*)E0, row, col,
                                  nnz, sBlocks, zBlocks, pBlocks);

    // 2 scaled-space propagation layers
    const int spmmGrid = (N_TOTAL * 8 + TB - 1) / TB;
    k_spmm<<<spmmGrid, TB>>>(X0, XA);   // XA = Dinv2 * (A @ X0)
    k_spmm<<<spmmGrid, TB>>>(XA, XB);   // XB = Dinv2 * (A @ XA)

    // fused layer 3 + gather
    int outThreads = 3 * BATCH * 8;
    k_out<<<(outThreads + TB - 1) / TB, TB>>>(users, pos, neg, E0, (float*)d_out);
}

// round 11
// speedup vs baseline: 2.9509x; 1.0617x over previous
#include <cuda_runtime.h>
#include <cuda_fp16.h>

#define N_USERS  100000
#define N_TOTAL  150000
#define DIM      64
#define BATCH    4096
#define NNZ_MAX  1400000     // 1.2M edges + up to 150k pad slots

#define SCAN_TILE 4096                                  // 1024 threads x 4 items
#define NB ((N_TOTAL + SCAN_TILE - 1) / SCAN_TILE)      // 37 blocks (all resident)

// Scaled-space embeddings X_k = d_inv ⊙ E_k, fp16, with one extra zero row
// (index N_TOTAL) used as the gather target of pad edges. All __device__
// globals are zero-initialized at module load; the sentinel rows are never
// written, so they stay zero. g_cnt and the scan flags are re-zeroed each call
// by the aux lane of k_prep_scatter (for the NEXT call).
__device__ __half g_X0[(N_TOTAL + 1) * DIM];
__device__ __half g_XA[(N_TOTAL + 1) * DIM];
__device__ __half g_XB[(N_TOTAL + 1) * DIM];
__device__ float g_dinv[N_TOTAL];        // (deg+1e-9)^-0.5
__device__ float g_dpos[N_TOTAL];        // (deg+1e-9)^+0.5  (to unscale)
__device__ int   g_cnt[N_TOTAL];         // true row degree (zeroed for next call)
__device__ int   g_rowptr[N_TOTAL + 1];  // padded exclusive scan (+ total at end)
__device__ int   g_rank[NNZ_MAX];        // intra-row rank per edge (from hist)
__device__ int   g_ecol[NNZ_MAX];        // CSR column indices; pad slots = N_TOTAL
__device__ int   g_blockAgg[64];
__device__ int   g_aggReady[64];

__device__ __forceinline__ __half2 u2h2(unsigned u) {
    __half2 h; *reinterpret_cast<unsigned*>(&h) = u; return h;
}
__device__ __forceinline__ unsigned h22u(__half2 h) {
    return *reinterpret_cast<unsigned*>(&h);
}

// ---------------------------------------------------------------------------
// histogram of row ids, capturing each edge's intra-row rank (4 edges/thread)
__global__ void k_hist(const int* __restrict__ row, int nnz) {
    int t = blockIdx.x * blockDim.x + threadIdx.x;
    int base = t * 4;
    if (base + 4 <= nnz) {
        int4 r = __ldg(reinterpret_cast<const int4*>(row + base));
        int4 k;
        k.x = atomicAdd(&g_cnt[r.x], 1);
        k.y = atomicAdd(&g_cnt[r.y], 1);
        k.z = atomicAdd(&g_cnt[r.z], 1);
        k.w = atomicAdd(&g_cnt[r.w], 1);
        *reinterpret_cast<int4*>(g_rank + base) = k;
    } else {
        for (int e = base; e < nnz; e++)
            g_rank[e] = atomicAdd(&g_cnt[__ldg(row + e)], 1);
    }
}

// single-pass exclusive scan of padded counts -> rowptr (incl. total at
// rowptr[N_TOTAL]); derives degree normalizers; writes pad-edge sentinels.
__global__ void k_scan() {
    __shared__ int warpsum[32];
    __shared__ int s_aggs[64];
    __shared__ int s_prev;
    int tid  = threadIdx.x;
    int lane = tid & 31, wid = tid >> 5;
    int base = blockIdx.x * SCAN_TILE + tid * 4;

    int cc[4], cp[4];
#pragma unroll
    for (int k = 0; k < 4; k++) {
        int idx = base + k;
        cc[k] = (idx < N_TOTAL) ? g_cnt[idx] : 0;
        cp[k] = (cc[k] + 1) & ~1;                 // padded to even
    }
    int t = cp[0] + cp[1] + cp[2] + cp[3];

    int x = t;
#pragma unroll
    for (int o = 1; o < 32; o <<= 1) {
        int y = __shfl_up_sync(0xffffffffu, x, o);
        if (lane >= o) x += y;
    }
    if (lane == 31) warpsum[wid] = x;
    __syncthreads();
    if (wid == 0) {
        int v = warpsum[lane];
#pragma unroll
        for (int o = 1; o < 32; o <<= 1) {
            int y = __shfl_up_sync(0xffffffffu, v, o);
            if (lane >= o) v += y;
        }
        warpsum[lane] = v;
    }
    __syncthreads();

    if (tid == 0) {
        g_blockAgg[blockIdx.x] = warpsum[31];
        __threadfence();
        atomicExch(&g_aggReady[blockIdx.x], 1);
    }
    if (tid < blockIdx.x) {
        while (atomicAdd(&g_aggReady[tid], 0) == 0) { }
        __threadfence();
        s_aggs[tid] = g_blockAgg[tid];
    }
    __syncthreads();
    if (tid == 0) {
        int p = 0;
        for (int j = 0; j < blockIdx.x; j++) p += s_aggs[j];
        s_prev = p;
    }
    __syncthreads();

    int woff = (wid == 0) ? 0 : warpsum[wid - 1];
    int run = s_prev + woff + (x - t);
#pragma unroll
    for (int k = 0; k < 4; k++) {
        int idx = base + k;
        if (idx < N_TOTAL) {
            g_rowptr[idx] = run;
            float degf = (float)cc[k] + 1e-9f;
            g_dinv[idx] = rsqrtf(degf);
            g_dpos[idx] = sqrtf(degf);
            if (cc[k] & 1) g_ecol[run + cc[k]] = N_TOTAL;   // pad -> zero row
            run += cp[k];
            if (idx == N_TOTAL - 1) g_rowptr[N_TOTAL] = run;  // total
        }
    }
}

// ---------------------------------------------------------------------------
// Fused scatter + prep + counter-rezero, blocks interleaved by modulo so every
// scheduling wave mixes L2-latency-bound scatter with DRAM-streaming prep.
__global__ void k_prep_scatter(const float4* __restrict__ E0,
                               const int* __restrict__ row,
                               const int* __restrict__ col,
                               int nnz, int sBlocks, int zBlocks, int pBlocks) {
    unsigned b = blockIdx.x;
    if ((b & 3u) == 0u) {
        int aux = b >> 2;
        if (aux < sBlocks) {
            // ---- scatter: 4 edges/thread, slot = rowptr[row] + rank[edge]
            int t = aux * blockDim.x + threadIdx.x;
            int base = t * 4;
            if (base + 4 <= nnz) {
                int4 r = __ldg(reinterpret_cast<const int4*>(row + base));
                int4 c = __ldg(reinterpret_cast<const int4*>(col + base));
                int4 k = *reinterpret_cast<const int4*>(g_rank + base);
                g_ecol[__ldg(g_rowptr + r.x) + k.x] = c.x;
                g_ecol[__ldg(g_rowptr + r.y) + k.y] = c.y;
                g_ecol[__ldg(g_rowptr + r.z) + k.z] = c.z;
                g_ecol[__ldg(g_rowptr + r.w) + k.w] = c.w;
            } else {
                for (int e = base; e < nnz; e++) {
                    int rr = __ldg(row + e);
                    g_ecol[__ldg(g_rowptr + rr) + g_rank[e]] = __ldg(col + e);
                }
            }
        } else if (aux < sBlocks + zBlocks) {
            // ---- zero g_cnt + scan flags for the NEXT call
            int zb = aux - sBlocks;
            int i = zb * blockDim.x + threadIdx.x;
            if (i < N_TOTAL / 4)
                reinterpret_cast<int4*>(g_cnt)[i] = make_int4(0, 0, 0, 0);
            if (zb == 0 && threadIdx.x < 16) {
                reinterpret_cast<int4*>(g_aggReady)[threadIdx.x] = make_int4(0, 0, 0, 0);
                reinterpret_cast<int4*>(g_blockAgg)[threadIdx.x] = make_int4(0, 0, 0, 0);
            }
        }
    } else {
        // ---- prep: X0 = fp16(d_inv[node] * E0), 8 floats per thread
        int pb = (int)b - (int)(b >> 2) - 1;     // rank among non-aux blocks
        if (pb >= pBlocks) return;
        int i = pb * blockDim.x + threadIdx.x;
        const int n8 = N_TOTAL * DIM / 8;
        if (i >= n8) return;
        float dv = __ldg(g_dinv + (i >> 3));     // 8 threads per node row
        float4 f0 = __ldg(E0 + i * 2);
        float4 f1 = __ldg(E0 + i * 2 + 1);
        uint4 h;
        h.x = h22u(__floats2half2_rn(dv * f0.x, dv * f0.y));
        h.y = h22u(__floats2half2_rn(dv * f0.z, dv * f0.w));
        h.z = h22u(__floats2half2_rn(dv * f1.x, dv * f1.y));
        h.w = h22u(__floats2half2_rn(dv * f1.z, dv * f1.w));
        reinterpret_cast<uint4*>(g_X0)[i] = h;
    }
}

// ---------------------------------------------------------------------------
// accumulate uint4 (8 halfs) into float2[4] — pure adds (used by k_out)
__device__ __forceinline__ void add_h8(float2 acc[4], uint4 h) {
    float2 p;
    p = __half22float2(u2h2(h.x)); acc[0].x += p.x; acc[0].y += p.y;
    p = __half22float2(u2h2(h.y)); acc[1].x += p.x; acc[1].y += p.y;
    p = __half22float2(u2h2(h.z)); acc[2].x += p.x; acc[2].y += p.y;
    p = __half22float2(u2h2(h.w)); acc[3].x += p.x; acc[3].y += p.y;
}

// scaled-space SpMM: dst[r] = d_inv[r]^2 * sum_{c in N(r)} src[c]
// 8 threads/row, 8 dims/lane. Inner loop combines each 4-edge group with an
// fp16 HADD2 tree (12 HADD2) and flushes once into fp32 accumulators
// (8 cvt + 8 FADD) — ~2.3x fewer FMA-pipe instructions than per-edge fp32.
__global__ void k_spmm(const __half* __restrict__ src, __half* __restrict__ dst) {
    int t = blockIdx.x * blockDim.x + threadIdx.x;
    int r = t >> 3;
    int q = t & 7;
    if (r >= N_TOTAL) return;

    int beg  = __ldg(g_rowptr + r);
    int cnt2 = __ldg(g_rowptr + r + 1) - beg;   // padded (even)
    const int* cp = g_ecol + beg;               // beg is even -> 8B aligned
    const uint4* src4 = reinterpret_cast<const uint4*>(src);

    float2 a0[4] = {{0,0},{0,0},{0,0},{0,0}};

    int i = 0;
    for (; i + 4 <= cnt2; i += 4) {
        int2 c01 = *reinterpret_cast<const int2*>(cp + i);
        int2 c23 = *reinterpret_cast<const int2*>(cp + i + 2);
        uint4 h0 = __ldg(src4 + (c01.x * 8 + q));
        uint4 h1 = __ldg(src4 + (c01.y * 8 + q));
        uint4 h2 = __ldg(src4 + (c23.x * 8 + q));
        uint4 h3 = __ldg(src4 + (c23.y * 8 + q));
        // fp16 pairwise tree: (h0+h1) + (h2+h3), then one fp32 flush
        __half2 tx = __hadd2(__hadd2(u2h2(h0.x), u2h2(h1.x)),
                             __hadd2(u2h2(h2.x), u2h2(h3.x)));
        __half2 ty = __hadd2(__hadd2(u2h2(h0.y), u2h2(h1.y)),
                             __hadd2(u2h2(h2.y), u2h2(h3.y)));
        __half2 tz = __hadd2(__hadd2(u2h2(h0.z), u2h2(h1.z)),
                             __hadd2(u2h2(h2.z), u2h2(h3.z)));
        __half2 tw = __hadd2(__hadd2(u2h2(h0.w), u2h2(h1.w)),
                             __hadd2(u2h2(h2.w), u2h2(h3.w)));
        float2 p;
        p = __half22float2(tx); a0[0].x += p.x; a0[0].y += p.y;
        p = __half22float2(ty); a0[1].x += p.x; a0[1].y += p.y;
        p = __half22float2(tz); a0[2].x += p.x; a0[2].y += p.y;
        p = __half22float2(tw); a0[3].x += p.x; a0[3].y += p.y;
    }
    if (i < cnt2) {   // exactly 2 edges remain (cnt2 is even)
        int2 c01 = *reinterpret_cast<const int2*>(cp + i);
        uint4 h0 = __ldg(src4 + (c01.x * 8 + q));
        uint4 h1 = __ldg(src4 + (c01.y * 8 + q));
        __half2 tx = __hadd2(u2h2(h0.x), u2h2(h1.x));
        __half2 ty = __hadd2(u2h2(h0.y), u2h2(h1.y));
        __half2 tz = __hadd2(u2h2(h0.z), u2h2(h1.z));
        __half2 tw = __hadd2(u2h2(h0.w), u2h2(h1.w));
        float2 p;
        p = __half22float2(tx); a0[0].x += p.x; a0[0].y += p.y;
        p = __half22float2(ty); a0[1].x += p.x; a0[1].y += p.y;
        p = __half22float2(tz); a0[2].x += p.x; a0[2].y += p.y;
        p = __half22float2(tw); a0[3].x += p.x; a0[3].y += p.y;
    }

    float dv = __ldg(g_dinv + r);
    float s = dv * dv;
    uint4 o;
    o.x = h22u(__floats2half2_rn(a0[0].x * s, a0[0].y * s));
    o.y = h22u(__floats2half2_rn(a0[1].x * s, a0[1].y * s));
    o.z = h22u(__floats2half2_rn(a0[2].x * s, a0[2].y * s));
    o.w = h22u(__floats2half2_rn(a0[3].x * s, a0[3].y * s));
    reinterpret_cast<uint4*>(dst)[r * 8 + q] = o;
}

// ---------------------------------------------------------------------------
// Fused layer-3 + output. For each gathered node:
//   sum3 = sum_{c in N(node)} XB[c]          (scaled-space layer-3 gather)
//   final = (E0 + (XA+XB)[node]*dpos + dinv*sum3) / 4 ;  also emit E0.
__global__ void k_out(const int* __restrict__ users, const int* __restrict__ pos,
                      const int* __restrict__ neg, const float* __restrict__ E0,
                      float* __restrict__ out) {
    int t = blockIdx.x * blockDim.x + threadIdx.x;
    if (t >= 3 * BATCH * 8) return;
    int s = t >> 15;            // BATCH*8 = 32768
    int rem = t & 32767;
    int b = rem >> 3;
    int q = rem & 7;

    int node;
    if (s == 0)      node = __ldg(users + b);
    else if (s == 1) node = N_USERS + __ldg(pos + b);
    else             node = N_USERS + __ldg(neg + b);

    int beg  = __ldg(g_rowptr + node);
    int cnt2 = __ldg(g_rowptr + node + 1) - beg;
    const int* cp = g_ecol + beg;
    const uint4* B4 = reinterpret_cast<const uint4*>(g_XB);

    float2 c0[4] = {{0,0},{0,0},{0,0},{0,0}};
    for (int i = 0; i < cnt2; i += 2) {
        int2 c01 = *reinterpret_cast<const int2*>(cp + i);
        uint4 h0 = __ldg(B4 + (c01.x * 8 + q));
        uint4 h1 = __ldg(B4 + (c01.y * 8 + q));
        add_h8(c0, h0);
        add_h8(c0, h1);
    }

    float dv = __ldg(g_dinv + node);
    float dp = __ldg(g_dpos + node);

    int off4 = node * 8 + q;
    uint4 ha = __ldg(reinterpret_cast<const uint4*>(g_XA) + off4);
    uint4 hb = __ldg(B4 + off4);
    size_t offf = (size_t)node * DIM + q * 8;
    float4 e00 = __ldg(reinterpret_cast<const float4*>(E0 + offf));
    float4 e01v = __ldg(reinterpret_cast<const float4*>(E0 + offf + 4));

    float2 pa, pb;
    float outv[8];
    pa = __half22float2(u2h2(ha.x)); pb = __half22float2(u2h2(hb.x));
    outv[0] = (e00.x + (pa.x + pb.x) * dp + dv * c0[0].x) * 0.25f;
    outv[1] = (e00.y + (pa.y + pb.y) * dp + dv * c0[0].y) * 0.25f;
    pa = __half22float2(u2h2(ha.y)); pb = __half22float2(u2h2(hb.y));
    outv[2] = (e00.z + (pa.x + pb.x) * dp + dv * c0[1].x) * 0.25f;
    outv[3] = (e00.w + (pa.y + pb.y) * dp + dv * c0[1].y) * 0.25f;
    pa = __half22float2(u2h2(ha.z)); pb = __half22float2(u2h2(hb.z));
    outv[4] = (e01v.x + (pa.x + pb.x) * dp + dv * c0[2].x) * 0.25f;
    outv[5] = (e01v.y + (pa.y + pb.y) * dp + dv * c0[2].y) * 0.25f;
    pa = __half22float2(u2h2(ha.w)); pb = __half22float2(u2h2(hb.w));
    outv[6] = (e01v.z + (pa.x + pb.x) * dp + dv * c0[3].x) * 0.25f;
    outv[7] = (e01v.w + (pa.y + pb.y) * dp + dv * c0[3].y) * 0.25f;

    const int S = BATCH * DIM;
    int o = b * DIM + q * 8;
    float4* op = reinterpret_cast<float4*>(out + (size_t)s * S + o);
    op[0] = make_float4(outv[0], outv[1], outv[2], outv[3]);
    op[1] = make_float4(outv[4], outv[5], outv[6], outv[7]);
    float4* oe = reinterpret_cast<float4*>(out + (size_t)(s + 3) * S + o);
    oe[0] = e00;
    oe[1] = e01v;
}

extern "C" void kernel_launch(void* const* d_in, const int* in_sizes, int n_in,
                              void* d_out, int out_size) {
    const int*   users = (const int*)d_in[0];
    const int*   pos   = (const int*)d_in[1];
    const int*   neg   = (const int*)d_in[2];
    const float* E0    = (const float*)d_in[3];
    const int*   row   = (const int*)d_in[4];
    const int*   col   = (const int*)d_in[5];
    const int    nnz   = in_sizes[4];

    __half *X0, *XA, *XB;
    cudaGetSymbolAddress((void**)&X0, g_X0);
    cudaGetSymbolAddress((void**)&XA, g_XA);
    cudaGetSymbolAddress((void**)&XB, g_XB);

    const int TB = 256;

    // CSR build + normalizers (counters zeroed by previous call / load-time init)
    int quads = (nnz + 3) / 4;
    k_hist<<<(quads + TB - 1) / TB, TB>>>(row, nnz);
    k_scan<<<NB, 1024>>>();

    // fused scatter + prep + re-zero, interleaved for intra-wave overlap
    const int n8 = N_TOTAL * DIM / 8;
    int sBlocks = (quads + TB - 1) / TB;
    int zBlocks = (N_TOTAL / 4 + TB - 1) / TB;
    int pBlocks = (n8 + TB - 1) / TB;
    int auxBlocks = sBlocks + zBlocks;
    int total = (pBlocks * 4 + 2) / 3;          // prep needs 3/4 of the grid
    if (total < auxBlocks * 4) total = auxBlocks * 4;
    total = (total + 3) & ~3;
    k_prep_scatter<<<total, TB>>>((const float4*)E0, row, col,
                                  nnz, sBlocks, zBlocks, pBlocks);

    // 2 scaled-space propagation layers
    const int spmmGrid = (N_TOTAL * 8 + TB - 1) / TB;
    k_spmm<<<spmmGrid, TB>>>(X0, XA);   // XA = Dinv2 * (A @ X0)
    k_spmm<<<spmmGrid, TB>>>(XA, XB);   // XB = Dinv2 * (A @ XA)

    // fused layer 3 + gather
    int outThreads = 3 * BATCH * 8;
    k_out<<<(outThreads + TB - 1) / TB, TB>>>(users, pos, neg, E0, (float*)d_out);
}

// round 12
// speedup vs baseline: 3.0200x; 1.0234x over previous
#include <cuda_runtime.h>
#include <cuda_fp16.h>

#define N_USERS  100000
#define N_TOTAL  150000
#define DIM      64
#define BATCH    4096
#define NNZ_MAX  1400000     // 1.2M edges + up to 150k pad slots

#define SCAN_TILE 4096                                  // 1024 threads x 4 items
#define NB ((N_TOTAL + SCAN_TILE - 1) / SCAN_TILE)      // 37 blocks (all resident)

// Scaled-space embeddings X_k = d_inv ⊙ E_k, fp16, with one extra zero row
// (index N_TOTAL) used as the gather target of pad edges. All __device__
// globals are zero-initialized at module load; the sentinel rows are never
// written, so they stay zero. g_cnt and the scan flags are re-zeroed each call
// by the aux lane of k_prep_scatter (for the NEXT call).
__device__ __half g_X0[(N_TOTAL + 1) * DIM];
__device__ __half g_XA[(N_TOTAL + 1) * DIM];
__device__ __half g_XB[(N_TOTAL + 1) * DIM];
__device__ float g_dinv[N_TOTAL];        // (deg+1e-9)^-0.5
__device__ float g_dpos[N_TOTAL];        // (deg+1e-9)^+0.5  (to unscale)
__device__ int   g_cnt[N_TOTAL];         // true row degree (zeroed for next call)
__device__ int   g_rowptr[N_TOTAL + 1];  // padded exclusive scan (+ total at end)
__device__ int   g_rank[NNZ_MAX];        // intra-row rank per edge (from hist)
__device__ int   g_ecol[NNZ_MAX];        // CSR column indices; pad slots = N_TOTAL
__device__ int   g_blockAgg[64];
__device__ int   g_aggReady[64];

__device__ __forceinline__ __half2 u2h2(unsigned u) {
    __half2 h; *reinterpret_cast<unsigned*>(&h) = u; return h;
}
__device__ __forceinline__ unsigned h22u(__half2 h) {
    return *reinterpret_cast<unsigned*>(&h);
}

// ---------------------------------------------------------------------------
// histogram of row ids, capturing each edge's intra-row rank (4 edges/thread)
__global__ void k_hist(const int* __restrict__ row, int nnz) {
    int t = blockIdx.x * blockDim.x + threadIdx.x;
    int base = t * 4;
    if (base + 4 <= nnz) {
        int4 r = __ldg(reinterpret_cast<const int4*>(row + base));
        int4 k;
        k.x = atomicAdd(&g_cnt[r.x], 1);
        k.y = atomicAdd(&g_cnt[r.y], 1);
        k.z = atomicAdd(&g_cnt[r.z], 1);
        k.w = atomicAdd(&g_cnt[r.w], 1);
        *reinterpret_cast<int4*>(g_rank + base) = k;
    } else {
        for (int e = base; e < nnz; e++)
            g_rank[e] = atomicAdd(&g_cnt[__ldg(row + e)], 1);
    }
}

// single-pass exclusive scan of padded counts -> rowptr (incl. total at
// rowptr[N_TOTAL]); derives degree normalizers; writes pad-edge sentinels.
__global__ void k_scan() {
    __shared__ int warpsum[32];
    __shared__ int s_aggs[64];
    __shared__ int s_prev;
    int tid  = threadIdx.x;
    int lane = tid & 31, wid = tid >> 5;
    int base = blockIdx.x * SCAN_TILE + tid * 4;

    int cc[4], cp[4];
#pragma unroll
    for (int k = 0; k < 4; k++) {
        int idx = base + k;
        cc[k] = (idx < N_TOTAL) ? g_cnt[idx] : 0;
        cp[k] = (cc[k] + 1) & ~1;                 // padded to even
    }
    int t = cp[0] + cp[1] + cp[2] + cp[3];

    int x = t;
#pragma unroll
    for (int o = 1; o < 32; o <<= 1) {
        int y = __shfl_up_sync(0xffffffffu, x, o);
        if (lane >= o) x += y;
    }
    if (lane == 31) warpsum[wid] = x;
    __syncthreads();
    if (wid == 0) {
        int v = warpsum[lane];
#pragma unroll
        for (int o = 1; o < 32; o <<= 1) {
            int y = __shfl_up_sync(0xffffffffu, v, o);
            if (lane >= o) v += y;
        }
        warpsum[lane] = v;
    }
    __syncthreads();

    if (tid == 0) {
        g_blockAgg[blockIdx.x] = warpsum[31];
        __threadfence();
        atomicExch(&g_aggReady[blockIdx.x], 1);
    }
    if (tid < blockIdx.x) {
        while (atomicAdd(&g_aggReady[tid], 0) == 0) { }
        __threadfence();
        s_aggs[tid] = g_blockAgg[tid];
    }
    __syncthreads();
    if (tid == 0) {
        int p = 0;
        for (int j = 0; j < blockIdx.x; j++) p += s_aggs[j];
        s_prev = p;
    }
    __syncthreads();

    int woff = (wid == 0) ? 0 : warpsum[wid - 1];
    int run = s_prev + woff + (x - t);
#pragma unroll
    for (int k = 0; k < 4; k++) {
        int idx = base + k;
        if (idx < N_TOTAL) {
            g_rowptr[idx] = run;
            float degf = (float)cc[k] + 1e-9f;
            g_dinv[idx] = rsqrtf(degf);
            g_dpos[idx] = sqrtf(degf);
            if (cc[k] & 1) g_ecol[run + cc[k]] = N_TOTAL;   // pad -> zero row
            run += cp[k];
            if (idx == N_TOTAL - 1) g_rowptr[N_TOTAL] = run;  // total
        }
    }
}

// ---------------------------------------------------------------------------
// Fused scatter + prep + counter-rezero, blocks interleaved by modulo so every
// scheduling wave mixes L2-latency-bound scatter with DRAM-streaming prep.
__global__ void k_prep_scatter(const float4* __restrict__ E0,
                               const int* __restrict__ row,
                               const int* __restrict__ col,
                               int nnz, int sBlocks, int zBlocks, int pBlocks) {
    unsigned b = blockIdx.x;
    if ((b & 3u) == 0u) {
        int aux = b >> 2;
        if (aux < sBlocks) {
            // ---- scatter: 4 edges/thread, slot = rowptr[row] + rank[edge]
            int t = aux * blockDim.x + threadIdx.x;
            int base = t * 4;
            if (base + 4 <= nnz) {
                int4 r = __ldg(reinterpret_cast<const int4*>(row + base));
                int4 c = __ldg(reinterpret_cast<const int4*>(col + base));
                int4 k = *reinterpret_cast<const int4*>(g_rank + base);
                g_ecol[__ldg(g_rowptr + r.x) + k.x] = c.x;
                g_ecol[__ldg(g_rowptr + r.y) + k.y] = c.y;
                g_ecol[__ldg(g_rowptr + r.z) + k.z] = c.z;
                g_ecol[__ldg(g_rowptr + r.w) + k.w] = c.w;
            } else {
                for (int e = base; e < nnz; e++) {
                    int rr = __ldg(row + e);
                    g_ecol[__ldg(g_rowptr + rr) + g_rank[e]] = __ldg(col + e);
                }
            }
        } else if (aux < sBlocks + zBlocks) {
            // ---- zero g_cnt + scan flags for the NEXT call
            int zb = aux - sBlocks;
            int i = zb * blockDim.x + threadIdx.x;
            if (i < N_TOTAL / 4)
                reinterpret_cast<int4*>(g_cnt)[i] = make_int4(0, 0, 0, 0);
            if (zb == 0 && threadIdx.x < 16) {
                reinterpret_cast<int4*>(g_aggReady)[threadIdx.x] = make_int4(0, 0, 0, 0);
                reinterpret_cast<int4*>(g_blockAgg)[threadIdx.x] = make_int4(0, 0, 0, 0);
            }
        }
    } else {
        // ---- prep: X0 = fp16(d_inv[node] * E0), 8 floats per thread
        int pb = (int)b - (int)(b >> 2) - 1;     // rank among non-aux blocks
        if (pb >= pBlocks) return;
        int i = pb * blockDim.x + threadIdx.x;
        const int n8 = N_TOTAL * DIM / 8;
        if (i >= n8) return;
        float dv = __ldg(g_dinv + (i >> 3));     // 8 threads per node row
        float4 f0 = __ldg(E0 + i * 2);
        float4 f1 = __ldg(E0 + i * 2 + 1);
        uint4 h;
        h.x = h22u(__floats2half2_rn(dv * f0.x, dv * f0.y));
        h.y = h22u(__floats2half2_rn(dv * f0.z, dv * f0.w));
        h.z = h22u(__floats2half2_rn(dv * f1.x, dv * f1.y));
        h.w = h22u(__floats2half2_rn(dv * f1.z, dv * f1.w));
        reinterpret_cast<uint4*>(g_X0)[i] = h;
    }
}

// ---------------------------------------------------------------------------
// scaled-space SpMM: dst[r] = d_inv[r]^2 * sum_{c in N(r)} src[c]
// 8 threads/row, 8 dims/lane. 4-edge HADD2 tree + single fp32 flush per group.
// __launch_bounds__(256, 8) caps regs at 32 -> 8 blocks/SM (occupancy push:
// profile showed latency-bound at occ=52%, no pipe near roofline).
__global__ void __launch_bounds__(256, 8)
k_spmm(const __half* __restrict__ src, __half* __restrict__ dst) {
    int t = blockIdx.x * blockDim.x + threadIdx.x;
    int r = t >> 3;
    int q = t & 7;
    if (r >= N_TOTAL) return;

    int beg  = __ldg(g_rowptr + r);
    int cnt2 = __ldg(g_rowptr + r + 1) - beg;   // padded (even)
    const int* cp = g_ecol + beg;               // beg is even -> 8B aligned
    const uint4* src4 = reinterpret_cast<const uint4*>(src);

    float2 a0[4] = {{0,0},{0,0},{0,0},{0,0}};

    int i = 0;
    for (; i + 4 <= cnt2; i += 4) {
        int2 c01 = *reinterpret_cast<const int2*>(cp + i);
        int2 c23 = *reinterpret_cast<const int2*>(cp + i + 2);
        uint4 h0 = __ldg(src4 + (c01.x * 8 + q));
        uint4 h1 = __ldg(src4 + (c01.y * 8 + q));
        uint4 h2 = __ldg(src4 + (c23.x * 8 + q));
        uint4 h3 = __ldg(src4 + (c23.y * 8 + q));
        __half2 tx = __hadd2(__hadd2(u2h2(h0.x), u2h2(h1.x)),
                             __hadd2(u2h2(h2.x), u2h2(h3.x)));
        __half2 ty = __hadd2(__hadd2(u2h2(h0.y), u2h2(h1.y)),
                             __hadd2(u2h2(h2.y), u2h2(h3.y)));
        __half2 tz = __hadd2(__hadd2(u2h2(h0.z), u2h2(h1.z)),
                             __hadd2(u2h2(h2.z), u2h2(h3.z)));
        __half2 tw = __hadd2(__hadd2(u2h2(h0.w), u2h2(h1.w)),
                             __hadd2(u2h2(h2.w), u2h2(h3.w)));
        float2 p;
        p = __half22float2(tx); a0[0].x += p.x; a0[0].y += p.y;
        p = __half22float2(ty); a0[1].x += p.x; a0[1].y += p.y;
        p = __half22float2(tz); a0[2].x += p.x; a0[2].y += p.y;
        p = __half22float2(tw); a0[3].x += p.x; a0[3].y += p.y;
    }
    if (i < cnt2) {   // exactly 2 edges remain (cnt2 is even)
        int2 c01 = *reinterpret_cast<const int2*>(cp + i);
        uint4 h0 = __ldg(src4 + (c01.x * 8 + q));
        uint4 h1 = __ldg(src4 + (c01.y * 8 + q));
        __half2 tx = __hadd2(u2h2(h0.x), u2h2(h1.x));
        __half2 ty = __hadd2(u2h2(h0.y), u2h2(h1.y));
        __half2 tz = __hadd2(u2h2(h0.z), u2h2(h1.z));
        __half2 tw = __hadd2(u2h2(h0.w), u2h2(h1.w));
        float2 p;
        p = __half22float2(tx); a0[0].x += p.x; a0[0].y += p.y;
        p = __half22float2(ty); a0[1].x += p.x; a0[1].y += p.y;
        p = __half22float2(tz); a0[2].x += p.x; a0[2].y += p.y;
        p = __half22float2(tw); a0[3].x += p.x; a0[3].y += p.y;
    }

    float dv = __ldg(g_dinv + r);
    float s = dv * dv;
    uint4 o;
    o.x = h22u(__floats2half2_rn(a0[0].x * s, a0[0].y * s));
    o.y = h22u(__floats2half2_rn(a0[1].x * s, a0[1].y * s));
    o.z = h22u(__floats2half2_rn(a0[2].x * s, a0[2].y * s));
    o.w = h22u(__floats2half2_rn(a0[3].x * s, a0[3].y * s));
    reinterpret_cast<uint4*>(dst)[r * 8 + q] = o;
}

// ---------------------------------------------------------------------------
// Fused layer-3 + output. For each gathered node:
//   sum3 = sum_{c in N(node)} XB[c]          (scaled-space layer-3 gather)
//   final = (E0 + (XA+XB)[node]*dpos + dinv*sum3) / 4 ;  also emit E0.
// Inner loop uses the same HADD2 pair trick as k_spmm.
__global__ void k_out(const int* __restrict__ users, const int* __restrict__ pos,
                      const int* __restrict__ neg, const float* __restrict__ E0,
                      float* __restrict__ out) {
    int t = blockIdx.x * blockDim.x + threadIdx.x;
    if (t >= 3 * BATCH * 8) return;
    int s = t >> 15;            // BATCH*8 = 32768
    int rem = t & 32767;
    int b = rem >> 3;
    int q = rem & 7;

    int node;
    if (s == 0)      node = __ldg(users + b);
    else if (s == 1) node = N_USERS + __ldg(pos + b);
    else             node = N_USERS + __ldg(neg + b);

    int beg  = __ldg(g_rowptr + node);
    int cnt2 = __ldg(g_rowptr + node + 1) - beg;
    const int* cp = g_ecol + beg;
    const uint4* B4 = reinterpret_cast<const uint4*>(g_XB);

    float2 c0[4] = {{0,0},{0,0},{0,0},{0,0}};
    for (int i = 0; i < cnt2; i += 2) {
        int2 c01 = *reinterpret_cast<const int2*>(cp + i);
        uint4 h0 = __ldg(B4 + (c01.x * 8 + q));
        uint4 h1 = __ldg(B4 + (c01.y * 8 + q));
        __half2 tx = __hadd2(u2h2(h0.x), u2h2(h1.x));
        __half2 ty = __hadd2(u2h2(h0.y), u2h2(h1.y));
        __half2 tz = __hadd2(u2h2(h0.z), u2h2(h1.z));
        __half2 tw = __hadd2(u2h2(h0.w), u2h2(h1.w));
        float2 p;
        p = __half22float2(tx); c0[0].x += p.x; c0[0].y += p.y;
        p = __half22float2(ty); c0[1].x += p.x; c0[1].y += p.y;
        p = __half22float2(tz); c0[2].x += p.x; c0[2].y += p.y;
        p = __half22float2(tw); c0[3].x += p.x; c0[3].y += p.y;
    }

    float dv = __ldg(g_dinv + node);
    float dp = __ldg(g_dpos + node);

    int off4 = node * 8 + q;
    uint4 ha = __ldg(reinterpret_cast<const uint4*>(g_XA) + off4);
    uint4 hb = __ldg(B4 + off4);
    size_t offf = (size_t)node * DIM + q * 8;
    float4 e00 = __ldg(reinterpret_cast<const float4*>(E0 + offf));
    float4 e01v = __ldg(reinterpret_cast<const float4*>(E0 + offf + 4));

    float2 pa, pb;
    float outv[8];
    pa = __half22float2(u2h2(ha.x)); pb = __half22float2(u2h2(hb.x));
    outv[0] = (e00.x + (pa.x + pb.x) * dp + dv * c0[0].x) * 0.25f;
    outv[1] = (e00.y + (pa.y + pb.y) * dp + dv * c0[0].y) * 0.25f;
    pa = __half22float2(u2h2(ha.y)); pb = __half22float2(u2h2(hb.y));
    outv[2] = (e00.z + (pa.x + pb.x) * dp + dv * c0[1].x) * 0.25f;
    outv[3] = (e00.w + (pa.y + pb.y) * dp + dv * c0[1].y) * 0.25f;
    pa = __half22float2(u2h2(ha.z)); pb = __half22float2(u2h2(hb.z));
    outv[4] = (e01v.x + (pa.x + pb.x) * dp + dv * c0[2].x) * 0.25f;
    outv[5] = (e01v.y + (pa.y + pb.y) * dp + dv * c0[2].y) * 0.25f;
    pa = __half22float2(u2h2(ha.w)); pb = __half22float2(u2h2(hb.w));
    outv[6] = (e01v.z + (pa.x + pb.x) * dp + dv * c0[3].x) * 0.25f;
    outv[7] = (e01v.w + (pa.y + pb.y) * dp + dv * c0[3].y) * 0.25f;

    const int S = BATCH * DIM;
    int o = b * DIM + q * 8;
    float4* op = reinterpret_cast<float4*>(out + (size_t)s * S + o);
    op[0] = make_float4(outv[0], outv[1], outv[2], outv[3]);
    op[1] = make_float4(outv[4], outv[5], outv[6], outv[7]);
    float4* oe = reinterpret_cast<float4*>(out + (size_t)(s + 3) * S + o);
    oe[0] = e00;
    oe[1] = e01v;
}

extern "C" void kernel_launch(void* const* d_in, const int* in_sizes, int n_in,
                              void* d_out, int out_size) {
    const int*   users = (const int*)d_in[0];
    const int*   pos   = (const int*)d_in[1];
    const int*   neg   = (const int*)d_in[2];
    const float* E0    = (const float*)d_in[3];
    const int*   row   = (const int*)d_in[4];
    const int*   col   = (const int*)d_in[5];
    const int    nnz   = in_sizes[4];

    __half *X0, *XA, *XB;
    cudaGetSymbolAddress((void**)&X0, g_X0);
    cudaGetSymbolAddress((void**)&XA, g_XA);
    cudaGetSymbolAddress((void**)&XB, g_XB);

    const int TB = 256;

    // CSR build + normalizers (counters zeroed by previous call / load-time init)
    int quads = (nnz + 3) / 4;
    k_hist<<<(quads + TB - 1) / TB, TB>>>(row, nnz);
    k_scan<<<NB, 1024>>>();

    // fused scatter + prep + re-zero, interleaved for intra-wave overlap
    const int n8 = N_TOTAL * DIM / 8;
    int sBlocks = (quads + TB - 1) / TB;
    int zBlocks = (N_TOTAL / 4 + TB - 1) / TB;
    int pBlocks = (n8 + TB - 1) / TB;
    int auxBlocks = sBlocks + zBlocks;
    int total = (pBlocks * 4 + 2) / 3;          // prep needs 3/4 of the grid
    if (total < auxBlocks * 4) total = auxBlocks * 4;
    total = (total + 3) & ~3;
    k_prep_scatter<<<total, TB>>>((const float4*)E0, row, col,
                                  nnz, sBlocks, zBlocks, pBlocks);

    // 2 scaled-space propagation layers
    const int spmmGrid = (N_TOTAL * 8 + TB - 1) / TB;
    k_spmm<<<spmmGrid, TB>>>(X0, XA);   // XA = Dinv2 * (A @ X0)
    k_spmm<<<spmmGrid, TB>>>(XA, XB);   // XB = Dinv2 * (A @ XA)

    // fused layer 3 + gather
    int outThreads = 3 * BATCH * 8;
    k_out<<<(outThreads + TB - 1) / TB, TB>>>(users, pos, neg, E0, (float*)d_out);
}